// round 12
// baseline (speedup 1.0000x reference)
#include <cuda_runtime.h>
#include <cuda_fp16.h>
#include <math.h>
#include <stdint.h>

typedef __half f16;

#define B_   16384
#define F_   32
#define V_   50000
#define DE   16
#define DIN  512
#define NE   6
#define H1_  512
#define H2_  256
#define T1_  128
#define T2_  64

// ---------------- scratch (device globals; no runtime alloc) ----------------
__device__ __align__(256) f16 g_Xf [(size_t)B_*DIN];
__device__ __align__(256) f16 g_Hf [(size_t)NE*B_*H1_];
__device__ __align__(256) f16 g_O  [(size_t)NE*B_*H2_];
__device__ __align__(256) f16 g_X2f[(size_t)3*B_*H2_];
__device__ __align__(256) f16 g_X3f[(size_t)2*B_*H2_];
__device__ __align__(256) f16 g_Tf [(size_t)2*B_*T1_];
__device__ __align__(256) float g_L1[(size_t)B_*128];      // level-1 gate logits (14 used)
__device__ __align__(256) float g_L2[(size_t)2*B_*128];    // level-2 gate logits (4 used each)
// transposed fp16 weights, layout [E, N, K] (K-major rows)
__device__ __align__(256) f16 g_w1[(size_t)NE*H1_*DIN];
__device__ __align__(256) f16 g_w2[(size_t)NE*H2_*H1_];
__device__ __align__(256) f16 g_w3[(size_t)NE*H1_*H2_];
__device__ __align__(256) f16 g_w4[(size_t)NE*H2_*H1_];
__device__ __align__(256) f16 g_w5[(size_t)2*T1_*H2_];
__device__ __align__(256) f16 g_w6[(size_t)2*T2_*T1_];
// packed gate weights (padded to N=128 rows) + padded biases
__device__ __align__(256) f16   g_wg1[(size_t)128*DIN];
__device__ __align__(256) f16   g_wg2[(size_t)2*128*H2_];
__device__ __align__(256) float g_b1p[128];
__device__ __align__(256) float g_b2p[2*128];

// ---------------- helpers ----------------
__device__ __forceinline__ uint32_t smem_u32(const void* p) {
    uint32_t a;
    asm("{ .reg .u64 t; cvta.to.shared.u64 t, %1; cvt.u32.u64 %0, t; }" : "=r"(a) : "l"(p));
    return a;
}
__device__ __forceinline__ void cp16(uint32_t dst, const void* src) {
    asm volatile("cp.async.cg.shared.global [%0], [%1], 16;" :: "r"(dst), "l"(src));
}
__device__ __forceinline__ void ldsm4(uint32_t* r, uint32_t a) {
    asm volatile("ldmatrix.sync.aligned.m8n8.x4.shared.b16 {%0,%1,%2,%3}, [%4];"
                 : "=r"(r[0]), "=r"(r[1]), "=r"(r[2]), "=r"(r[3]) : "r"(a));
}
__device__ __forceinline__ void mma16816(float* c, const uint32_t* a, const uint32_t* b) {
    asm volatile("mma.sync.aligned.m16n8k16.row.col.f32.f16.f16.f32 "
                 "{%0,%1,%2,%3}, {%4,%5,%6,%7}, {%8,%9}, {%0,%1,%2,%3};"
                 : "+f"(c[0]), "+f"(c[1]), "+f"(c[2]), "+f"(c[3])
                 : "r"(a[0]), "r"(a[1]), "r"(a[2]), "r"(a[3]), "r"(b[0]), "r"(b[1]));
}
__device__ __forceinline__ uint32_t swz(uint32_t off) { return off ^ ((off >> 3) & 0x70); }

// ---------------- fp16 grouped GEMM, 4 warps, 64x(NT/2) warp tiles, 2-stage pipe --------
// Main slices (e < eGate): C[e] = act(A[aidx] @ B[e]^T + bias[e])
// Gate slices (e >= eGate, blockIdx.x==0 only): logits = A[e-eGate] @ gateB[e-eGate]^T + gBias
//   written fp32 to gC + (e-eGate)*B_*128, ldc=128, no activation.
// NT: CTA N-tile (128/64). ACT: 0=relu 1=sigmoid. OUTM: 0=f32, 1=f16.
template<int NT, int ACT, int OUTM>
__global__ void __launch_bounds__(128, 2)
gemm_mma(const f16* __restrict__ A, const f16* __restrict__ B,
         const float* __restrict__ bias,
         float* __restrict__ Cf, f16* __restrict__ Ch,
         int K, int Ntot, int a_sel, size_t aStride, size_t cStride, int ldc,
         int eGate, const f16* __restrict__ gateB, const float* __restrict__ gBias,
         float* __restrict__ gC)
{
    extern __shared__ char smem_raw[];
    constexpr int ASTG  = 128 * 128;
    constexpr int BSTG  = NT * 128;
    constexpr int STAGE = ASTG + BSTG;
    constexpr int WN    = NT / 2;
    constexpr int NJ    = WN / 8;
    constexpr int NB    = WN / 16;

    const int e = blockIdx.z;
    const bool isGate = (eGate >= 0) && (e >= eGate);
    if (isGate && blockIdx.x != 0) return;       // gate output is 128 cols only
    const int gsel = isGate ? (e - eGate) : 0;

    const int tid  = threadIdx.x;
    const int wid  = tid >> 5;
    const int lane = tid & 31;
    const int m0 = blockIdx.y * 128;
    const int n0 = blockIdx.x * NT;

    const int aidx = isGate ? gsel
                   : ((a_sel == 0) ? 0 : ((a_sel == 1) ? (e >> 1) : e));
    const f16* pA = A + (size_t)aidx * aStride + (size_t)m0 * K;
    const f16* pB = isGate ? (gateB + (size_t)gsel * 128 * K)
                           : (B + ((size_t)e * Ntot + n0) * K);

    const uint32_t sb = smem_u32(smem_raw);

    const int wm = wid >> 1, wn = wid & 1;
    const int mw = wm * 64;
    const int nw = wn * WN;

    float acc[4][NJ][4];
    #pragma unroll
    for (int i = 0; i < 4; i++)
        #pragma unroll
        for (int j = 0; j < NJ; j++)
            #pragma unroll
            for (int q = 0; q < 4; q++) acc[i][j][q] = 0.f;

    auto load_stage = [&](int kt, int st) {
        const uint32_t base = sb + st * STAGE;
        const int k0 = kt * 64;
        #pragma unroll
        for (int t = 0; t < 8; t++) {
            int id = tid + t * 128;
            int r = id >> 3, q = id & 7;
            uint32_t off = swz((uint32_t)(r * 128 + q * 16));
            cp16(base + off, pA + (size_t)r * K + k0 + q * 8);
        }
        #pragma unroll
        for (int t = 0; t < NT / 16; t++) {
            int id = tid + t * 128;
            int r = id >> 3, q = id & 7;
            uint32_t off = swz((uint32_t)(r * 128 + q * 16));
            cp16(base + ASTG + off, pB + (size_t)r * K + k0 + q * 8);
        }
        asm volatile("cp.async.commit_group;" ::: "memory");
    };

    load_stage(0, 0);
    const int T = K >> 6;
    for (int kt = 0; kt < T; kt++) {
        if (kt + 1 < T) {
            load_stage(kt + 1, (kt + 1) & 1);
            asm volatile("cp.async.wait_group 1;" ::: "memory");
        } else {
            asm volatile("cp.async.wait_group 0;" ::: "memory");
        }
        __syncthreads();

        const uint32_t abase = sb + (kt & 1) * STAGE;
        const uint32_t bbase = abase + ASTG;

        #pragma unroll
        for (int ks = 0; ks < 4; ks++) {
            const int cb = ks * 32 + (lane >> 4) * 16;
            uint32_t af[4][4];
            #pragma unroll
            for (int i = 0; i < 4; i++) {
                int row = mw + i * 16 + (lane & 15);
                ldsm4(af[i], abase + swz((uint32_t)(row * 128 + cb)));
            }
            uint32_t bf[NJ][2];
            #pragma unroll
            for (int bb = 0; bb < NB; bb++) {
                int row = nw + bb * 16 + (lane & 15);
                uint32_t tr[4];
                ldsm4(tr, bbase + swz((uint32_t)(row * 128 + cb)));
                bf[2*bb][0] = tr[0]; bf[2*bb+1][0] = tr[1];
                bf[2*bb][1] = tr[2]; bf[2*bb+1][1] = tr[3];
            }
            #pragma unroll
            for (int i = 0; i < 4; i++)
                #pragma unroll
                for (int j = 0; j < NJ; j++)
                    mma16816(acc[i][j], af[i], bf[j]);
        }
        __syncthreads();
    }

    // epilogue
    const int lr  = lane >> 2;
    const int lc2 = (lane & 3) * 2;
    #pragma unroll
    for (int i = 0; i < 4; i++)
        #pragma unroll
        for (int j = 0; j < NJ; j++) {
            int col = n0 + nw + j * 8 + lc2;
            float b0, b1;
            if (isGate) { b0 = __ldg(gBias + gsel * 128 + col); b1 = __ldg(gBias + gsel * 128 + col + 1); }
            else        { b0 = __ldg(bias + (size_t)e * Ntot + col); b1 = __ldg(bias + (size_t)e * Ntot + col + 1); }
            #pragma unroll
            for (int h = 0; h < 2; h++) {
                int row = m0 + mw + i * 16 + lr + h * 8;
                float v0 = acc[i][j][2 * h + 0] + b0;
                float v1 = acc[i][j][2 * h + 1] + b1;
                if (isGate) {
                    *reinterpret_cast<float2*>(gC + (size_t)gsel * B_ * 128 +
                                               (size_t)row * 128 + col) = make_float2(v0, v1);
                    continue;
                }
                if (ACT == 0) { v0 = fmaxf(v0, 0.f); v1 = fmaxf(v1, 0.f); }
                else { v0 = 1.f / (1.f + __expf(-v0)); v1 = 1.f / (1.f + __expf(-v1)); }
                size_t gi = (size_t)e * cStride + (size_t)row * ldc + col;
                if (OUTM == 0) {
                    *reinterpret_cast<float2*>(Cf + gi) = make_float2(v0, v1);
                } else {
                    *reinterpret_cast<__half2*>(Ch + gi) = __floats2half2_rn(v0, v1);
                }
            }
        }
}

// ---------------- merged prep: weight transpose + gather + gate pack ----------------
#define WCONV_BLKS 3920
#define GATH_BLKS  2048
#define GPACK_N    (128*DIN + 2*128*H2_ + 128 + 256)
#define GPACK_BLKS ((GPACK_N + 255) / 256)

__global__ void prep_all(const float* __restrict__ s1, const float* __restrict__ s2,
                         const float* __restrict__ s3, const float* __restrict__ s4,
                         const float* __restrict__ s5, const float* __restrict__ s6,
                         const int* __restrict__ ids, const float* __restrict__ emb,
                         const float* __restrict__ Wst1, const float* __restrict__ bst1,
                         const float* __restrict__ Wsh1, const float* __restrict__ bsh1,
                         const float* __restrict__ Wst2, const float* __restrict__ bst2)
{
    __shared__ float t[32][33];
    int b = blockIdx.x;
    int tid = threadIdx.x;

    if (b < WCONV_BLKS) {
        const float* src; f16* dst; int K, N, loc;
        if (b < 1536)      { src = s1; dst = g_w1; K = DIN; N = H1_; loc = b; }
        else if (b < 2304) { src = s2; dst = g_w2; K = H1_; N = H2_; loc = b - 1536; }
        else if (b < 3072) { src = s3; dst = g_w3; K = H2_; N = H1_; loc = b - 2304; }
        else if (b < 3840) { src = s4; dst = g_w4; K = H1_; N = H2_; loc = b - 3072; }
        else if (b < 3904) { src = s5; dst = g_w5; K = H2_; N = T1_; loc = b - 3840; }
        else               { src = s6; dst = g_w6; K = T1_; N = T2_; loc = b - 3904; }
        int tX = N >> 5, tY = K >> 5;
        int e  = loc / (tX * tY);
        int r  = loc % (tX * tY);
        int k0 = (r / tX) * 32, n0 = (r % tX) * 32;
        int tx = tid & 31, ty = tid >> 5;
        #pragma unroll
        for (int j = 0; j < 4; j++)
            t[ty + 8 * j][tx] = src[((size_t)e * K + k0 + ty + 8 * j) * N + n0 + tx];
        __syncthreads();
        #pragma unroll
        for (int j = 0; j < 4; j++) {
            int n = n0 + ty + 8 * j, k = k0 + tx;
            dst[((size_t)e * N + n) * K + k] = __float2half_rn(t[tx][ty + 8 * j]);
        }
    } else if (b < WCONV_BLKS + GATH_BLKS) {
        int idx = (b - WCONV_BLKS) * 256 + tid;      // b*F + f
        int f  = idx & (F_ - 1);
        int id = ids[idx];
        const float4* src = reinterpret_cast<const float4*>(emb + ((size_t)f * V_ + id) * DE);
        float4 v0 = src[0], v1 = src[1], v2 = src[2], v3 = src[3];
        __align__(16) f16 hv[16];
        float vals[16] = {v0.x,v0.y,v0.z,v0.w, v1.x,v1.y,v1.z,v1.w,
                          v2.x,v2.y,v2.z,v2.w, v3.x,v3.y,v3.z,v3.w};
        #pragma unroll
        for (int j = 0; j < 16; j++) hv[j] = __float2half_rn(vals[j]);
        uint4* dh = reinterpret_cast<uint4*>(g_Xf + (size_t)idx * DE);
        dh[0] = ((uint4*)hv)[0]; dh[1] = ((uint4*)hv)[1];
    } else {
        int idx = (b - WCONV_BLKS - GATH_BLKS) * 256 + tid;
        if (idx < 128 * DIN) {                                  // wg1: [128, 512]
            int r = idx / DIN, d = idx % DIN;
            float v = 0.f;
            if (r < 8)       v = Wst1[(size_t)(r >> 2) * DIN * 4 + d * 4 + (r & 3)];
            else if (r < 14) v = Wsh1[(size_t)d * 6 + (r - 8)];
            g_wg1[(size_t)r * DIN + d] = __float2half_rn(v);
        } else if (idx < 128 * DIN + 2 * 128 * H2_) {           // wg2: [2, 128, 256]
            int q = idx - 128 * DIN;
            int tsk = q / (128 * H2_);
            int rr  = q % (128 * H2_);
            int r = rr / H2_, d = rr % H2_;
            float v = (r < 4) ? Wst2[(size_t)tsk * H2_ * 4 + d * 4 + r] : 0.f;
            g_wg2[((size_t)tsk * 128 + r) * H2_ + d] = __float2half_rn(v);
        } else if (idx < 128 * DIN + 2 * 128 * H2_ + 128) {     // b1p[128]
            int i = idx - (128 * DIN + 2 * 128 * H2_);
            g_b1p[i] = (i < 8) ? bst1[i] : ((i < 14) ? bsh1[i - 8] : 0.f);
        } else if (idx < GPACK_N) {                             // b2p[2*128]
            int i = idx - (128 * DIN + 2 * 128 * H2_ + 128);
            int tsk = i >> 7, k = i & 127;
            g_b2p[i] = (k < 4) ? bst2[tsk * 4 + k] : 0.f;
        }
    }
}

// ---------------- level-1 combine (half2-vectorized) ----------------
__global__ void comb1_kernel() {
    int warp = threadIdx.x >> 5, lane = threadIdx.x & 31;
    int b = blockIdx.x * 8 + warp;

    float lg[14];
    #pragma unroll
    for (int i = 0; i < 14; i++) lg[i] = __ldg(g_L1 + (size_t)b * 128 + i);

    float g0[4], g1[4], gs[6];
    {
        float m = fmaxf(fmaxf(lg[0], lg[1]), fmaxf(lg[2], lg[3]));
        float s = 0.f;
        #pragma unroll
        for (int k = 0; k < 4; k++) { g0[k] = __expf(lg[k] - m); s += g0[k]; }
        #pragma unroll
        for (int k = 0; k < 4; k++) g0[k] /= s;
    }
    {
        float m = fmaxf(fmaxf(lg[4], lg[5]), fmaxf(lg[6], lg[7]));
        float s = 0.f;
        #pragma unroll
        for (int k = 0; k < 4; k++) { g1[k] = __expf(lg[4 + k] - m); s += g1[k]; }
        #pragma unroll
        for (int k = 0; k < 4; k++) g1[k] /= s;
    }
    {
        float m = lg[8];
        #pragma unroll
        for (int k = 9; k < 14; k++) m = fmaxf(m, lg[k]);
        float s = 0.f;
        #pragma unroll
        for (int k = 0; k < 6; k++) { gs[k] = __expf(lg[8 + k] - m); s += gs[k]; }
        #pragma unroll
        for (int k = 0; k < 6; k++) gs[k] /= s;
    }

    const __half2* O2 = reinterpret_cast<const __half2*>(g_O);
    __half2* X22 = reinterpret_cast<__half2*>(g_X2f);
    #pragma unroll
    for (int it = 0; it < 4; it++) {
        int c = lane + 32 * it;                       // half2 index, 0..127
        float2 v[6];
        #pragma unroll
        for (int e = 0; e < 6; e++)
            v[e] = __half22float2(O2[((size_t)e * B_ + b) * (H2_ / 2) + c]);
        float o0x = g0[0]*v[0].x + g0[1]*v[1].x + g0[2]*v[4].x + g0[3]*v[5].x;
        float o0y = g0[0]*v[0].y + g0[1]*v[1].y + g0[2]*v[4].y + g0[3]*v[5].y;
        float o1x = g1[0]*v[2].x + g1[1]*v[3].x + g1[2]*v[4].x + g1[3]*v[5].x;
        float o1y = g1[0]*v[2].y + g1[1]*v[3].y + g1[2]*v[4].y + g1[3]*v[5].y;
        float osx = 0.f, osy = 0.f;
        #pragma unroll
        for (int e = 0; e < 6; e++) { osx += gs[e] * v[e].x; osy += gs[e] * v[e].y; }
        X22[((size_t)0 * B_ + b) * (H2_ / 2) + c] = __floats2half2_rn(o0x, o0y);
        X22[((size_t)1 * B_ + b) * (H2_ / 2) + c] = __floats2half2_rn(o1x, o1y);
        X22[((size_t)2 * B_ + b) * (H2_ / 2) + c] = __floats2half2_rn(osx, osy);
    }
}

// ---------------- level-2 combine (half2-vectorized) ----------------
__global__ void comb2_kernel() {
    int warp = threadIdx.x >> 5, lane = threadIdx.x & 31;
    int b = blockIdx.x * 8 + warp;

    float l0[4], l1[4];
    #pragma unroll
    for (int k = 0; k < 4; k++) {
        l0[k] = __ldg(g_L2 + ((size_t)0 * B_ + b) * 128 + k);
        l1[k] = __ldg(g_L2 + ((size_t)1 * B_ + b) * 128 + k);
    }

    float g0[4], g1[4];
    {
        float m = fmaxf(fmaxf(l0[0], l0[1]), fmaxf(l0[2], l0[3]));
        float s = 0.f;
        #pragma unroll
        for (int k = 0; k < 4; k++) { g0[k] = __expf(l0[k] - m); s += g0[k]; }
        #pragma unroll
        for (int k = 0; k < 4; k++) g0[k] /= s;
    }
    {
        float m = fmaxf(fmaxf(l1[0], l1[1]), fmaxf(l1[2], l1[3]));
        float s = 0.f;
        #pragma unroll
        for (int k = 0; k < 4; k++) { g1[k] = __expf(l1[k] - m); s += g1[k]; }
        #pragma unroll
        for (int k = 0; k < 4; k++) g1[k] /= s;
    }

    const __half2* O2 = reinterpret_cast<const __half2*>(g_O);
    __half2* X32 = reinterpret_cast<__half2*>(g_X3f);
    #pragma unroll
    for (int it = 0; it < 4; it++) {
        int c = lane + 32 * it;
        float2 v[6];
        #pragma unroll
        for (int e = 0; e < 6; e++)
            v[e] = __half22float2(O2[((size_t)e * B_ + b) * (H2_ / 2) + c]);
        float o0x = g0[0]*v[0].x + g0[1]*v[1].x + g0[2]*v[4].x + g0[3]*v[5].x;
        float o0y = g0[0]*v[0].y + g0[1]*v[1].y + g0[2]*v[4].y + g0[3]*v[5].y;
        float o1x = g1[0]*v[2].x + g1[1]*v[3].x + g1[2]*v[4].x + g1[3]*v[5].x;
        float o1y = g1[0]*v[2].y + g1[1]*v[3].y + g1[2]*v[4].y + g1[3]*v[5].y;
        X32[((size_t)0 * B_ + b) * (H2_ / 2) + c] = __floats2half2_rn(o0x, o0y);
        X32[((size_t)1 * B_ + b) * (H2_ / 2) + c] = __floats2half2_rn(o1x, o1y);
    }
}

// ---------------- launcher ----------------
extern "C" void kernel_launch(void* const* d_in, const int* in_sizes, int n_in,
                              void* d_out, int out_size) {
    const int*   x_ids = (const int*)  d_in[0];
    const float* emb   = (const float*)d_in[1];
    const float* e1_W1 = (const float*)d_in[2];
    const float* e1_b1 = (const float*)d_in[3];
    const float* e1_W2 = (const float*)d_in[4];
    const float* e1_b2 = (const float*)d_in[5];
    const float* g1_Ws = (const float*)d_in[6];
    const float* g1_bs = (const float*)d_in[7];
    const float* g1_Wsh= (const float*)d_in[8];
    const float* g1_bsh= (const float*)d_in[9];
    const float* e2_W1 = (const float*)d_in[10];
    const float* e2_b1 = (const float*)d_in[11];
    const float* e2_W2 = (const float*)d_in[12];
    const float* e2_b2 = (const float*)d_in[13];
    const float* g2_Ws = (const float*)d_in[14];
    const float* g2_bs = (const float*)d_in[15];
    const float* tw_W1 = (const float*)d_in[16];
    const float* tw_b1 = (const float*)d_in[17];
    const float* tw_W2 = (const float*)d_in[18];
    const float* tw_b2 = (const float*)d_in[19];

    f16 *pXf,*pHf,*pO,*pX2f,*pX3f,*pTf,*w1,*w2,*w3,*w4,*w5,*w6,*wg1,*wg2;
    float *pL1,*pL2,*b1p,*b2p;
    cudaGetSymbolAddress((void**)&pXf,  g_Xf);
    cudaGetSymbolAddress((void**)&pHf,  g_Hf);
    cudaGetSymbolAddress((void**)&pO,   g_O);
    cudaGetSymbolAddress((void**)&pX2f, g_X2f);
    cudaGetSymbolAddress((void**)&pX3f, g_X3f);
    cudaGetSymbolAddress((void**)&pTf,  g_Tf);
    cudaGetSymbolAddress((void**)&pL1,  g_L1);
    cudaGetSymbolAddress((void**)&pL2,  g_L2);
    cudaGetSymbolAddress((void**)&w1, g_w1);
    cudaGetSymbolAddress((void**)&w2, g_w2);
    cudaGetSymbolAddress((void**)&w3, g_w3);
    cudaGetSymbolAddress((void**)&w4, g_w4);
    cudaGetSymbolAddress((void**)&w5, g_w5);
    cudaGetSymbolAddress((void**)&w6, g_w6);
    cudaGetSymbolAddress((void**)&wg1, g_wg1);
    cudaGetSymbolAddress((void**)&wg2, g_wg2);
    cudaGetSymbolAddress((void**)&b1p, g_b1p);
    cudaGetSymbolAddress((void**)&b2p, g_b2p);

    const int SM128 = 2 * (128 * 128 + 128 * 128);   // 65536 (2 stages)
    const int SM64  = 2 * (128 * 128 + 64 * 128);    // 49152
    cudaFuncSetAttribute((const void*)gemm_mma<128,0,1>, cudaFuncAttributeMaxDynamicSharedMemorySize, SM128);
    cudaFuncSetAttribute((const void*)gemm_mma<64,1,0>,  cudaFuncAttributeMaxDynamicSharedMemorySize, SM64);

    // prep (single launch: weight transpose + gather + gate pack — all coalesced)
    prep_all<<<WCONV_BLKS + GATH_BLKS + GPACK_BLKS, 256>>>(
        e1_W1, e1_W2, e2_W1, e2_W2, tw_W1, tw_W2,
        x_ids, emb, g1_Ws, g1_bs, g1_Wsh, g1_bsh, g2_Ws, g2_bs);

    // L1 experts stage 1 + fused gate1 logits (z=6)
    gemm_mma<128,0,1><<<dim3(H1_/128, B_/128, NE + 1), 128, SM128>>>(
        pXf, w1, e1_b1, nullptr, pHf, DIN, H1_, 0, 0, (size_t)B_*H1_, H1_,
        /*eGate=*/NE, wg1, b1p, pL1);
    // L1 experts stage 2
    gemm_mma<128,0,1><<<dim3(H2_/128, B_/128, NE), 128, SM128>>>(
        pHf, w2, e1_b2, nullptr, pO, H1_, H2_, 2, (size_t)B_*H1_, (size_t)B_*H2_, H2_,
        -1, nullptr, nullptr, nullptr);
    // L1 combine
    comb1_kernel<<<B_/8, 256>>>();

    // L2 experts stage 1 + fused gate2 logits (z=6,7; A = X2[0], X2[1])
    gemm_mma<128,0,1><<<dim3(H1_/128, B_/128, NE + 2), 128, SM128>>>(
        pX2f, w3, e2_b1, nullptr, pHf, H2_, H1_, 1, (size_t)B_*H2_, (size_t)B_*H1_, H1_,
        /*eGate=*/NE, wg2, b2p, pL2);
    // L2 experts stage 2
    gemm_mma<128,0,1><<<dim3(H2_/128, B_/128, NE), 128, SM128>>>(
        pHf, w4, e2_b2, nullptr, pO, H1_, H2_, 2, (size_t)B_*H1_, (size_t)B_*H2_, H2_,
        -1, nullptr, nullptr, nullptr);
    // L2 combine
    comb2_kernel<<<B_/8, 256>>>();

    // towers
    gemm_mma<128,0,1><<<dim3(T1_/128, B_/128, 2), 128, SM128>>>(
        pX3f, w5, tw_b1, nullptr, pTf, H2_, T1_, 2, (size_t)B_*H2_, (size_t)B_*T1_, T1_,
        -1, nullptr, nullptr, nullptr);
    gemm_mma<64,1,0><<<dim3(T2_/64, B_/128, 2), 128, SM64>>>(
        pTf, w6, tw_b2, (float*)d_out, nullptr, T1_, T2_, 2, (size_t)B_*T1_, (size_t)T2_, 2*T2_,
        -1, nullptr, nullptr, nullptr);
}

// round 13
// speedup vs baseline: 1.0252x; 1.0252x over previous
#include <cuda_runtime.h>
#include <cuda_fp16.h>
#include <math.h>
#include <stdint.h>

typedef __half f16;

#define B_   16384
#define F_   32
#define V_   50000
#define DE   16
#define DIN  512
#define NE   6
#define H1_  512
#define H2_  256
#define T1_  128
#define T2_  64

// ---------------- scratch (device globals; no runtime alloc) ----------------
__device__ __align__(256) f16 g_Xf [(size_t)B_*DIN];
__device__ __align__(256) f16 g_Hf [(size_t)NE*B_*H1_];
__device__ __align__(256) f16 g_O  [(size_t)NE*B_*H2_];
__device__ __align__(256) f16 g_X2f[(size_t)3*B_*H2_];
__device__ __align__(256) f16 g_X3f[(size_t)2*B_*H2_];
__device__ __align__(256) f16 g_Tf [(size_t)2*B_*T1_];
__device__ __align__(256) float g_L1[(size_t)B_*64];
__device__ __align__(256) float g_L2[(size_t)2*B_*64];
// transposed fp16 weights, layout [E, N, K] (K-major rows)
__device__ __align__(256) f16 g_w1[(size_t)NE*H1_*DIN];
__device__ __align__(256) f16 g_w2[(size_t)NE*H2_*H1_];
__device__ __align__(256) f16 g_w3[(size_t)NE*H1_*H2_];
__device__ __align__(256) f16 g_w4[(size_t)NE*H2_*H1_];
__device__ __align__(256) f16 g_w5[(size_t)2*T1_*H2_];
__device__ __align__(256) f16 g_w6[(size_t)2*T2_*T1_];
// packed gate weights (padded to N=64) + biases
__device__ __align__(256) f16   g_wg1[(size_t)64*DIN];
__device__ __align__(256) f16   g_wg2[(size_t)2*64*H2_];
__device__ __align__(256) float g_b1p[64];
__device__ __align__(256) float g_b2p[128];

// ---------------- helpers ----------------
__device__ __forceinline__ uint32_t smem_u32(const void* p) {
    uint32_t a;
    asm("{ .reg .u64 t; cvta.to.shared.u64 t, %1; cvt.u32.u64 %0, t; }" : "=r"(a) : "l"(p));
    return a;
}
__device__ __forceinline__ void cp16(uint32_t dst, const void* src) {
    asm volatile("cp.async.cg.shared.global [%0], [%1], 16;" :: "r"(dst), "l"(src));
}
__device__ __forceinline__ void ldsm4(uint32_t* r, uint32_t a) {
    asm volatile("ldmatrix.sync.aligned.m8n8.x4.shared.b16 {%0,%1,%2,%3}, [%4];"
                 : "=r"(r[0]), "=r"(r[1]), "=r"(r[2]), "=r"(r[3]) : "r"(a));
}
__device__ __forceinline__ void mma16816(float* c, const uint32_t* a, const uint32_t* b) {
    asm volatile("mma.sync.aligned.m16n8k16.row.col.f32.f16.f16.f32 "
                 "{%0,%1,%2,%3}, {%4,%5,%6,%7}, {%8,%9}, {%0,%1,%2,%3};"
                 : "+f"(c[0]), "+f"(c[1]), "+f"(c[2]), "+f"(c[3])
                 : "r"(a[0]), "r"(a[1]), "r"(a[2]), "r"(a[3]), "r"(b[0]), "r"(b[1]));
}
__device__ __forceinline__ uint32_t swz(uint32_t off) { return off ^ ((off >> 3) & 0x70); }

// ---------------- fp16 grouped GEMM, 4 warps, 64x(NT/2) warp tiles, 2-stage pipe --------
// C[e] = act(A[aidx] @ B[e]^T + bias[e])
// NT: CTA N-tile (128/64). ACT: 0=relu 1=sigmoid 2=none. OUTM: 0=f32, 1=f16.
template<int NT, int ACT, int OUTM>
__global__ void __launch_bounds__(128, 2)
gemm_mma(const f16* __restrict__ A, const f16* __restrict__ B,
         const float* __restrict__ bias,
         float* __restrict__ Cf, f16* __restrict__ Ch,
         int K, int Ntot, int a_sel, size_t aStride, size_t cStride, int ldc)
{
    extern __shared__ char smem_raw[];
    constexpr int ASTG  = 128 * 128;
    constexpr int BSTG  = NT * 128;
    constexpr int STAGE = ASTG + BSTG;
    constexpr int WN    = NT / 2;
    constexpr int NJ    = WN / 8;
    constexpr int NB    = WN / 16;

    const int tid  = threadIdx.x;
    const int wid  = tid >> 5;
    const int lane = tid & 31;
    const int e  = blockIdx.z;
    const int m0 = blockIdx.y * 128;
    const int n0 = blockIdx.x * NT;

    const int aidx = (a_sel == 0) ? 0 : ((a_sel == 1) ? (e >> 1) : e);
    const f16* pA = A + (size_t)aidx * aStride + (size_t)m0 * K;
    const f16* pB = B + ((size_t)e * Ntot + n0) * K;

    const uint32_t sb = smem_u32(smem_raw);

    const int wm = wid >> 1, wn = wid & 1;
    const int mw = wm * 64;
    const int nw = wn * WN;

    float acc[4][NJ][4];
    #pragma unroll
    for (int i = 0; i < 4; i++)
        #pragma unroll
        for (int j = 0; j < NJ; j++)
            #pragma unroll
            for (int q = 0; q < 4; q++) acc[i][j][q] = 0.f;

    auto load_stage = [&](int kt, int st) {
        const uint32_t base = sb + st * STAGE;
        const int k0 = kt * 64;
        #pragma unroll
        for (int t = 0; t < 8; t++) {
            int id = tid + t * 128;
            int r = id >> 3, q = id & 7;
            uint32_t off = swz((uint32_t)(r * 128 + q * 16));
            cp16(base + off, pA + (size_t)r * K + k0 + q * 8);
        }
        #pragma unroll
        for (int t = 0; t < NT / 16; t++) {
            int id = tid + t * 128;
            int r = id >> 3, q = id & 7;
            uint32_t off = swz((uint32_t)(r * 128 + q * 16));
            cp16(base + ASTG + off, pB + (size_t)r * K + k0 + q * 8);
        }
        asm volatile("cp.async.commit_group;" ::: "memory");
    };

    load_stage(0, 0);
    const int T = K >> 6;
    for (int kt = 0; kt < T; kt++) {
        if (kt + 1 < T) {
            load_stage(kt + 1, (kt + 1) & 1);
            asm volatile("cp.async.wait_group 1;" ::: "memory");
        } else {
            asm volatile("cp.async.wait_group 0;" ::: "memory");
        }
        __syncthreads();

        const uint32_t abase = sb + (kt & 1) * STAGE;
        const uint32_t bbase = abase + ASTG;

        #pragma unroll
        for (int ks = 0; ks < 4; ks++) {
            const int cb = ks * 32 + (lane >> 4) * 16;
            uint32_t af[4][4];
            #pragma unroll
            for (int i = 0; i < 4; i++) {
                int row = mw + i * 16 + (lane & 15);
                ldsm4(af[i], abase + swz((uint32_t)(row * 128 + cb)));
            }
            uint32_t bf[NJ][2];
            #pragma unroll
            for (int bb = 0; bb < NB; bb++) {
                int row = nw + bb * 16 + (lane & 15);
                uint32_t tr[4];
                ldsm4(tr, bbase + swz((uint32_t)(row * 128 + cb)));
                bf[2*bb][0] = tr[0]; bf[2*bb+1][0] = tr[1];
                bf[2*bb][1] = tr[2]; bf[2*bb+1][1] = tr[3];
            }
            #pragma unroll
            for (int i = 0; i < 4; i++)
                #pragma unroll
                for (int j = 0; j < NJ; j++)
                    mma16816(acc[i][j], af[i], bf[j]);
        }
        __syncthreads();
    }

    // epilogue
    const int lr  = lane >> 2;
    const int lc2 = (lane & 3) * 2;
    #pragma unroll
    for (int i = 0; i < 4; i++)
        #pragma unroll
        for (int j = 0; j < NJ; j++) {
            int col = n0 + nw + j * 8 + lc2;
            float b0 = __ldg(bias + (size_t)e * Ntot + col);
            float b1 = __ldg(bias + (size_t)e * Ntot + col + 1);
            #pragma unroll
            for (int h = 0; h < 2; h++) {
                int row = m0 + mw + i * 16 + lr + h * 8;
                float v0 = acc[i][j][2 * h + 0] + b0;
                float v1 = acc[i][j][2 * h + 1] + b1;
                if (ACT == 0) { v0 = fmaxf(v0, 0.f); v1 = fmaxf(v1, 0.f); }
                else if (ACT == 1) { v0 = 1.f / (1.f + __expf(-v0)); v1 = 1.f / (1.f + __expf(-v1)); }
                size_t gi = (size_t)e * cStride + (size_t)row * ldc + col;
                if (OUTM == 0) {
                    *reinterpret_cast<float2*>(Cf + gi) = make_float2(v0, v1);
                } else {
                    *reinterpret_cast<__half2*>(Ch + gi) = __floats2half2_rn(v0, v1);
                }
            }
        }
}

// ---------------- merged prep: weight transpose + gather + gate pack ----------------
#define WCONV_BLKS 3920
#define GATH_BLKS  2048
#define GPACK_BLKS 257

__global__ void prep_all(const float* __restrict__ s1, const float* __restrict__ s2,
                         const float* __restrict__ s3, const float* __restrict__ s4,
                         const float* __restrict__ s5, const float* __restrict__ s6,
                         const int* __restrict__ ids, const float* __restrict__ emb,
                         const float* __restrict__ Wst1, const float* __restrict__ bst1,
                         const float* __restrict__ Wsh1, const float* __restrict__ bsh1,
                         const float* __restrict__ Wst2, const float* __restrict__ bst2)
{
    __shared__ float t[32][33];
    int b = blockIdx.x;
    int tid = threadIdx.x;

    if (b < WCONV_BLKS) {
        const float* src; f16* dst; int K, N, loc;
        if (b < 1536)      { src = s1; dst = g_w1; K = DIN; N = H1_; loc = b; }
        else if (b < 2304) { src = s2; dst = g_w2; K = H1_; N = H2_; loc = b - 1536; }
        else if (b < 3072) { src = s3; dst = g_w3; K = H2_; N = H1_; loc = b - 2304; }
        else if (b < 3840) { src = s4; dst = g_w4; K = H1_; N = H2_; loc = b - 3072; }
        else if (b < 3904) { src = s5; dst = g_w5; K = H2_; N = T1_; loc = b - 3840; }
        else               { src = s6; dst = g_w6; K = T1_; N = T2_; loc = b - 3904; }
        int tX = N >> 5, tY = K >> 5;
        int e  = loc / (tX * tY);
        int r  = loc % (tX * tY);
        int k0 = (r / tX) * 32, n0 = (r % tX) * 32;
        int tx = tid & 31, ty = tid >> 5;
        #pragma unroll
        for (int j = 0; j < 4; j++)
            t[ty + 8 * j][tx] = src[((size_t)e * K + k0 + ty + 8 * j) * N + n0 + tx];
        __syncthreads();
        #pragma unroll
        for (int j = 0; j < 4; j++) {
            int n = n0 + ty + 8 * j, k = k0 + tx;
            dst[((size_t)e * N + n) * K + k] = __float2half_rn(t[tx][ty + 8 * j]);
        }
    } else if (b < WCONV_BLKS + GATH_BLKS) {
        int idx = (b - WCONV_BLKS) * 256 + tid;      // b*F + f
        int f  = idx & (F_ - 1);
        int id = ids[idx];
        const float4* src = reinterpret_cast<const float4*>(emb + ((size_t)f * V_ + id) * DE);
        float4 v0 = src[0], v1 = src[1], v2 = src[2], v3 = src[3];
        __align__(16) f16 hv[16];
        float vals[16] = {v0.x,v0.y,v0.z,v0.w, v1.x,v1.y,v1.z,v1.w,
                          v2.x,v2.y,v2.z,v2.w, v3.x,v3.y,v3.z,v3.w};
        #pragma unroll
        for (int j = 0; j < 16; j++) hv[j] = __float2half_rn(vals[j]);
        uint4* dh = reinterpret_cast<uint4*>(g_Xf + (size_t)idx * DE);
        dh[0] = ((uint4*)hv)[0]; dh[1] = ((uint4*)hv)[1];
    } else {
        int idx = (b - WCONV_BLKS - GATH_BLKS) * 256 + tid;
        if (idx < 64 * DIN) {
            int r = idx / DIN, d = idx % DIN;
            float v = 0.f;
            if (r < 8)       v = Wst1[(size_t)(r >> 2) * DIN * 4 + d * 4 + (r & 3)];
            else if (r < 14) v = Wsh1[(size_t)d * 6 + (r - 8)];
            g_wg1[(size_t)r * DIN + d] = __float2half_rn(v);
        } else if (idx < 64 * DIN + 2 * 64 * H2_) {
            int q = idx - 64 * DIN;
            int tsk = q / (64 * H2_);
            int rr  = q % (64 * H2_);
            int r = rr / H2_, d = rr % H2_;
            float v = (r < 4) ? Wst2[(size_t)tsk * H2_ * 4 + d * 4 + r] : 0.f;
            g_wg2[((size_t)tsk * 64 + r) * H2_ + d] = __float2half_rn(v);
        } else if (idx < 64 * DIN + 2 * 64 * H2_ + 64) {
            int i = idx - (64 * DIN + 2 * 64 * H2_);
            g_b1p[i] = (i < 8) ? bst1[i] : ((i < 14) ? bsh1[i - 8] : 0.f);
        } else if (idx < 64 * DIN + 2 * 64 * H2_ + 64 + 128) {
            int i = idx - (64 * DIN + 2 * 64 * H2_ + 64);
            int tsk = i >> 6, k = i & 63;
            g_b2p[i] = (k < 4) ? bst2[tsk * 4 + k] : 0.f;
        }
    }
}

// ---------------- level-1 combine (half2-vectorized) ----------------
__global__ void comb1_kernel() {
    int warp = threadIdx.x >> 5, lane = threadIdx.x & 31;
    int b = blockIdx.x * 8 + warp;

    float lg[14];
    #pragma unroll
    for (int i = 0; i < 14; i++) lg[i] = __ldg(g_L1 + (size_t)b * 64 + i);

    float g0[4], g1[4], gs[6];
    {
        float m = fmaxf(fmaxf(lg[0], lg[1]), fmaxf(lg[2], lg[3]));
        float s = 0.f;
        #pragma unroll
        for (int k = 0; k < 4; k++) { g0[k] = __expf(lg[k] - m); s += g0[k]; }
        #pragma unroll
        for (int k = 0; k < 4; k++) g0[k] /= s;
    }
    {
        float m = fmaxf(fmaxf(lg[4], lg[5]), fmaxf(lg[6], lg[7]));
        float s = 0.f;
        #pragma unroll
        for (int k = 0; k < 4; k++) { g1[k] = __expf(lg[4 + k] - m); s += g1[k]; }
        #pragma unroll
        for (int k = 0; k < 4; k++) g1[k] /= s;
    }
    {
        float m = lg[8];
        #pragma unroll
        for (int k = 9; k < 14; k++) m = fmaxf(m, lg[k]);
        float s = 0.f;
        #pragma unroll
        for (int k = 0; k < 6; k++) { gs[k] = __expf(lg[8 + k] - m); s += gs[k]; }
        #pragma unroll
        for (int k = 0; k < 6; k++) gs[k] /= s;
    }

    const __half2* O2 = reinterpret_cast<const __half2*>(g_O);
    __half2* X22 = reinterpret_cast<__half2*>(g_X2f);
    #pragma unroll
    for (int it = 0; it < 4; it++) {
        int c = lane + 32 * it;                       // half2 index, 0..127
        float2 v[6];
        #pragma unroll
        for (int e = 0; e < 6; e++)
            v[e] = __half22float2(O2[((size_t)e * B_ + b) * (H2_ / 2) + c]);
        float o0x = g0[0]*v[0].x + g0[1]*v[1].x + g0[2]*v[4].x + g0[3]*v[5].x;
        float o0y = g0[0]*v[0].y + g0[1]*v[1].y + g0[2]*v[4].y + g0[3]*v[5].y;
        float o1x = g1[0]*v[2].x + g1[1]*v[3].x + g1[2]*v[4].x + g1[3]*v[5].x;
        float o1y = g1[0]*v[2].y + g1[1]*v[3].y + g1[2]*v[4].y + g1[3]*v[5].y;
        float osx = 0.f, osy = 0.f;
        #pragma unroll
        for (int e = 0; e < 6; e++) { osx += gs[e] * v[e].x; osy += gs[e] * v[e].y; }
        X22[((size_t)0 * B_ + b) * (H2_ / 2) + c] = __floats2half2_rn(o0x, o0y);
        X22[((size_t)1 * B_ + b) * (H2_ / 2) + c] = __floats2half2_rn(o1x, o1y);
        X22[((size_t)2 * B_ + b) * (H2_ / 2) + c] = __floats2half2_rn(osx, osy);
    }
}

// ---------------- level-2 combine (half2-vectorized) ----------------
__global__ void comb2_kernel() {
    int warp = threadIdx.x >> 5, lane = threadIdx.x & 31;
    int b = blockIdx.x * 8 + warp;

    float l0[4], l1[4];
    #pragma unroll
    for (int k = 0; k < 4; k++) {
        l0[k] = __ldg(g_L2 + ((size_t)0 * B_ + b) * 64 + k);
        l1[k] = __ldg(g_L2 + ((size_t)1 * B_ + b) * 64 + k);
    }

    float g0[4], g1[4];
    {
        float m = fmaxf(fmaxf(l0[0], l0[1]), fmaxf(l0[2], l0[3]));
        float s = 0.f;
        #pragma unroll
        for (int k = 0; k < 4; k++) { g0[k] = __expf(l0[k] - m); s += g0[k]; }
        #pragma unroll
        for (int k = 0; k < 4; k++) g0[k] /= s;
    }
    {
        float m = fmaxf(fmaxf(l1[0], l1[1]), fmaxf(l1[2], l1[3]));
        float s = 0.f;
        #pragma unroll
        for (int k = 0; k < 4; k++) { g1[k] = __expf(l1[k] - m); s += g1[k]; }
        #pragma unroll
        for (int k = 0; k < 4; k++) g1[k] /= s;
    }

    const __half2* O2 = reinterpret_cast<const __half2*>(g_O);
    __half2* X32 = reinterpret_cast<__half2*>(g_X3f);
    #pragma unroll
    for (int it = 0; it < 4; it++) {
        int c = lane + 32 * it;
        float2 v[6];
        #pragma unroll
        for (int e = 0; e < 6; e++)
            v[e] = __half22float2(O2[((size_t)e * B_ + b) * (H2_ / 2) + c]);
        float o0x = g0[0]*v[0].x + g0[1]*v[1].x + g0[2]*v[4].x + g0[3]*v[5].x;
        float o0y = g0[0]*v[0].y + g0[1]*v[1].y + g0[2]*v[4].y + g0[3]*v[5].y;
        float o1x = g1[0]*v[2].x + g1[1]*v[3].x + g1[2]*v[4].x + g1[3]*v[5].x;
        float o1y = g1[0]*v[2].y + g1[1]*v[3].y + g1[2]*v[4].y + g1[3]*v[5].y;
        X32[((size_t)0 * B_ + b) * (H2_ / 2) + c] = __floats2half2_rn(o0x, o0y);
        X32[((size_t)1 * B_ + b) * (H2_ / 2) + c] = __floats2half2_rn(o1x, o1y);
    }
}

// ---------------- launcher ----------------
extern "C" void kernel_launch(void* const* d_in, const int* in_sizes, int n_in,
                              void* d_out, int out_size) {
    const int*   x_ids = (const int*)  d_in[0];
    const float* emb   = (const float*)d_in[1];
    const float* e1_W1 = (const float*)d_in[2];
    const float* e1_b1 = (const float*)d_in[3];
    const float* e1_W2 = (const float*)d_in[4];
    const float* e1_b2 = (const float*)d_in[5];
    const float* g1_Ws = (const float*)d_in[6];
    const float* g1_bs = (const float*)d_in[7];
    const float* g1_Wsh= (const float*)d_in[8];
    const float* g1_bsh= (const float*)d_in[9];
    const float* e2_W1 = (const float*)d_in[10];
    const float* e2_b1 = (const float*)d_in[11];
    const float* e2_W2 = (const float*)d_in[12];
    const float* e2_b2 = (const float*)d_in[13];
    const float* g2_Ws = (const float*)d_in[14];
    const float* g2_bs = (const float*)d_in[15];
    const float* tw_W1 = (const float*)d_in[16];
    const float* tw_b1 = (const float*)d_in[17];
    const float* tw_W2 = (const float*)d_in[18];
    const float* tw_b2 = (const float*)d_in[19];

    f16 *pXf,*pHf,*pO,*pX2f,*pX3f,*pTf,*w1,*w2,*w3,*w4,*w5,*w6,*wg1,*wg2;
    float *pL1,*pL2,*b1p,*b2p;
    cudaGetSymbolAddress((void**)&pXf,  g_Xf);
    cudaGetSymbolAddress((void**)&pHf,  g_Hf);
    cudaGetSymbolAddress((void**)&pO,   g_O);
    cudaGetSymbolAddress((void**)&pX2f, g_X2f);
    cudaGetSymbolAddress((void**)&pX3f, g_X3f);
    cudaGetSymbolAddress((void**)&pTf,  g_Tf);
    cudaGetSymbolAddress((void**)&pL1,  g_L1);
    cudaGetSymbolAddress((void**)&pL2,  g_L2);
    cudaGetSymbolAddress((void**)&w1, g_w1);
    cudaGetSymbolAddress((void**)&w2, g_w2);
    cudaGetSymbolAddress((void**)&w3, g_w3);
    cudaGetSymbolAddress((void**)&w4, g_w4);
    cudaGetSymbolAddress((void**)&w5, g_w5);
    cudaGetSymbolAddress((void**)&w6, g_w6);
    cudaGetSymbolAddress((void**)&wg1, g_wg1);
    cudaGetSymbolAddress((void**)&wg2, g_wg2);
    cudaGetSymbolAddress((void**)&b1p, g_b1p);
    cudaGetSymbolAddress((void**)&b2p, g_b2p);

    const int SM128 = 2 * (128 * 128 + 128 * 128);   // 65536 (2 stages)
    const int SM64  = 2 * (128 * 128 + 64 * 128);    // 49152
    cudaFuncSetAttribute((const void*)gemm_mma<128,0,1>, cudaFuncAttributeMaxDynamicSharedMemorySize, SM128);
    cudaFuncSetAttribute((const void*)gemm_mma<64,2,0>,  cudaFuncAttributeMaxDynamicSharedMemorySize, SM64);
    cudaFuncSetAttribute((const void*)gemm_mma<64,1,0>,  cudaFuncAttributeMaxDynamicSharedMemorySize, SM64);

    // prep (single launch: weight transpose + gather + gate pack — all coalesced)
    prep_all<<<WCONV_BLKS + GATH_BLKS + GPACK_BLKS, 256>>>(
        e1_W1, e1_W2, e2_W1, e2_W2, tw_W1, tw_W2,
        x_ids, emb, g1_Ws, g1_bs, g1_Wsh, g1_bsh, g2_Ws, g2_bs);

    // L1 experts
    gemm_mma<128,0,1><<<dim3(H1_/128, B_/128, NE), 128, SM128>>>(
        pXf, w1, e1_b1, nullptr, pHf, DIN, H1_, 0, 0, (size_t)B_*H1_, H1_);
    gemm_mma<128,0,1><<<dim3(H2_/128, B_/128, NE), 128, SM128>>>(
        pHf, w2, e1_b2, nullptr, pO, H1_, H2_, 2, (size_t)B_*H1_, (size_t)B_*H2_, H2_);
    // L1 gate logits + combine
    gemm_mma<64,2,0><<<dim3(1, B_/128, 1), 128, SM64>>>(
        pXf, wg1, b1p, pL1, nullptr, DIN, 64, 0, 0, 0, 64);
    comb1_kernel<<<B_/8, 256>>>();

    // L2 experts
    gemm_mma<128,0,1><<<dim3(H1_/128, B_/128, NE), 128, SM128>>>(
        pX2f, w3, e2_b1, nullptr, pHf, H2_, H1_, 1, (size_t)B_*H2_, (size_t)B_*H1_, H1_);
    gemm_mma<128,0,1><<<dim3(H2_/128, B_/128, NE), 128, SM128>>>(
        pHf, w4, e2_b2, nullptr, pO, H1_, H2_, 2, (size_t)B_*H1_, (size_t)B_*H2_, H2_);
    // L2 gate logits + combine
    gemm_mma<64,2,0><<<dim3(1, B_/128, 2), 128, SM64>>>(
        pX2f, wg2, b2p, pL2, nullptr, H2_, 64, 2, (size_t)B_*H2_, (size_t)B_*64, 64);
    comb2_kernel<<<B_/8, 256>>>();

    // towers
    gemm_mma<128,0,1><<<dim3(T1_/128, B_/128, 2), 128, SM128>>>(
        pX3f, w5, tw_b1, nullptr, pTf, H2_, T1_, 2, (size_t)B_*H2_, (size_t)B_*T1_, T1_);
    gemm_mma<64,1,0><<<dim3(T2_/64, B_/128, 2), 128, SM64>>>(
        pTf, w6, tw_b2, (float*)d_out, nullptr, T1_, T2_, 2, (size_t)B_*T1_, (size_t)T2_, 2*T2_);
}

// round 14
// speedup vs baseline: 1.0324x; 1.0071x over previous
#include <cuda_runtime.h>
#include <cuda_fp16.h>
#include <math.h>
#include <stdint.h>

typedef __half f16;

#define B_   16384
#define F_   32
#define V_   50000
#define DE   16
#define DIN  512
#define NE   6
#define H1_  512
#define H2_  256
#define T1_  128
#define T2_  64

// ---------------- scratch (device globals; no runtime alloc) ----------------
__device__ __align__(256) f16 g_Xf [(size_t)B_*DIN];
__device__ __align__(256) f16 g_Hf [(size_t)NE*B_*H1_];
__device__ __align__(256) f16 g_O  [(size_t)NE*B_*H2_];
__device__ __align__(256) f16 g_X2f[(size_t)3*B_*H2_];
__device__ __align__(256) f16 g_X3f[(size_t)2*B_*H2_];
__device__ __align__(256) f16 g_Tf [(size_t)2*B_*T1_];
__device__ __align__(256) float g_L1[(size_t)B_*64];
__device__ __align__(256) float g_L2[(size_t)2*B_*64];
// transposed fp16 weights, layout [E, N, K] (K-major rows)
__device__ __align__(256) f16 g_w1[(size_t)NE*H1_*DIN];
__device__ __align__(256) f16 g_w2[(size_t)NE*H2_*H1_];
__device__ __align__(256) f16 g_w3[(size_t)NE*H1_*H2_];
__device__ __align__(256) f16 g_w4[(size_t)NE*H2_*H1_];
__device__ __align__(256) f16 g_w5[(size_t)2*T1_*H2_];
__device__ __align__(256) f16 g_w6[(size_t)2*T2_*T1_];
// packed gate weights (padded to N=64) + biases
__device__ __align__(256) f16   g_wg1[(size_t)64*DIN];
__device__ __align__(256) f16   g_wg2[(size_t)2*64*H2_];
__device__ __align__(256) float g_b1p[64];
__device__ __align__(256) float g_b2p[128];

// ---------------- helpers ----------------
__device__ __forceinline__ uint32_t smem_u32(const void* p) {
    uint32_t a;
    asm("{ .reg .u64 t; cvta.to.shared.u64 t, %1; cvt.u32.u64 %0, t; }" : "=r"(a) : "l"(p));
    return a;
}
__device__ __forceinline__ void cp16(uint32_t dst, const void* src) {
    asm volatile("cp.async.cg.shared.global [%0], [%1], 16;" :: "r"(dst), "l"(src));
}
__device__ __forceinline__ void ldsm4(uint32_t* r, uint32_t a) {
    asm volatile("ldmatrix.sync.aligned.m8n8.x4.shared.b16 {%0,%1,%2,%3}, [%4];"
                 : "=r"(r[0]), "=r"(r[1]), "=r"(r[2]), "=r"(r[3]) : "r"(a));
}
__device__ __forceinline__ void mma16816(float* c, const uint32_t* a, const uint32_t* b) {
    asm volatile("mma.sync.aligned.m16n8k16.row.col.f32.f16.f16.f32 "
                 "{%0,%1,%2,%3}, {%4,%5,%6,%7}, {%8,%9}, {%0,%1,%2,%3};"
                 : "+f"(c[0]), "+f"(c[1]), "+f"(c[2]), "+f"(c[3])
                 : "r"(a[0]), "r"(a[1]), "r"(a[2]), "r"(a[3]), "r"(b[0]), "r"(b[1]));
}
__device__ __forceinline__ uint32_t swz(uint32_t off) { return off ^ ((off >> 3) & 0x70); }

// ---------------- fp16 grouped GEMM, 4 warps, 64x(NT/2) warp tiles, 2-stage pipe --------
// C[e] = act(A[aidx] @ B[e]^T + bias[e])
// NT: CTA N-tile (128/64). ACT: 0=relu 1=sigmoid 2=none. OUTM: 0=f32, 1=f16.
template<int NT, int ACT, int OUTM>
__global__ void __launch_bounds__(128, 2)
gemm_mma(const f16* __restrict__ A, const f16* __restrict__ B,
         const float* __restrict__ bias,
         float* __restrict__ Cf, f16* __restrict__ Ch,
         int K, int Ntot, int a_sel, size_t aStride, size_t cStride, int ldc)
{
    extern __shared__ char smem_raw[];
    constexpr int ASTG  = 128 * 128;
    constexpr int BSTG  = NT * 128;
    constexpr int STAGE = ASTG + BSTG;
    constexpr int WN    = NT / 2;
    constexpr int NJ    = WN / 8;
    constexpr int NB    = WN / 16;

    const int tid  = threadIdx.x;
    const int wid  = tid >> 5;
    const int lane = tid & 31;
    const int e  = blockIdx.z;
    const int m0 = blockIdx.y * 128;
    const int n0 = blockIdx.x * NT;

    const int aidx = (a_sel == 0) ? 0 : ((a_sel == 1) ? (e >> 1) : e);
    const f16* pA = A + (size_t)aidx * aStride + (size_t)m0 * K;
    const f16* pB = B + ((size_t)e * Ntot + n0) * K;

    const uint32_t sb = smem_u32(smem_raw);

    const int wm = wid >> 1, wn = wid & 1;
    const int mw = wm * 64;
    const int nw = wn * WN;

    float acc[4][NJ][4];
    #pragma unroll
    for (int i = 0; i < 4; i++)
        #pragma unroll
        for (int j = 0; j < NJ; j++)
            #pragma unroll
            for (int q = 0; q < 4; q++) acc[i][j][q] = 0.f;

    auto load_stage = [&](int kt, int st) {
        const uint32_t base = sb + st * STAGE;
        const int k0 = kt * 64;
        #pragma unroll
        for (int t = 0; t < 8; t++) {
            int id = tid + t * 128;
            int r = id >> 3, q = id & 7;
            uint32_t off = swz((uint32_t)(r * 128 + q * 16));
            cp16(base + off, pA + (size_t)r * K + k0 + q * 8);
        }
        #pragma unroll
        for (int t = 0; t < NT / 16; t++) {
            int id = tid + t * 128;
            int r = id >> 3, q = id & 7;
            uint32_t off = swz((uint32_t)(r * 128 + q * 16));
            cp16(base + ASTG + off, pB + (size_t)r * K + k0 + q * 8);
        }
        asm volatile("cp.async.commit_group;" ::: "memory");
    };

    load_stage(0, 0);
    const int T = K >> 6;
    for (int kt = 0; kt < T; kt++) {
        if (kt + 1 < T) {
            load_stage(kt + 1, (kt + 1) & 1);
            asm volatile("cp.async.wait_group 1;" ::: "memory");
        } else {
            asm volatile("cp.async.wait_group 0;" ::: "memory");
        }
        __syncthreads();

        const uint32_t abase = sb + (kt & 1) * STAGE;
        const uint32_t bbase = abase + ASTG;

        #pragma unroll
        for (int ks = 0; ks < 4; ks++) {
            const int cb = ks * 32 + (lane >> 4) * 16;
            uint32_t af[4][4];
            #pragma unroll
            for (int i = 0; i < 4; i++) {
                int row = mw + i * 16 + (lane & 15);
                ldsm4(af[i], abase + swz((uint32_t)(row * 128 + cb)));
            }
            uint32_t bf[NJ][2];
            #pragma unroll
            for (int bb = 0; bb < NB; bb++) {
                int row = nw + bb * 16 + (lane & 15);
                uint32_t tr[4];
                ldsm4(tr, bbase + swz((uint32_t)(row * 128 + cb)));
                bf[2*bb][0] = tr[0]; bf[2*bb+1][0] = tr[1];
                bf[2*bb][1] = tr[2]; bf[2*bb+1][1] = tr[3];
            }
            #pragma unroll
            for (int i = 0; i < 4; i++)
                #pragma unroll
                for (int j = 0; j < NJ; j++)
                    mma16816(acc[i][j], af[i], bf[j]);
        }
        __syncthreads();
    }

    // epilogue
    const int lr  = lane >> 2;
    const int lc2 = (lane & 3) * 2;
    #pragma unroll
    for (int i = 0; i < 4; i++)
        #pragma unroll
        for (int j = 0; j < NJ; j++) {
            int col = n0 + nw + j * 8 + lc2;
            float b0 = __ldg(bias + (size_t)e * Ntot + col);
            float b1 = __ldg(bias + (size_t)e * Ntot + col + 1);
            #pragma unroll
            for (int h = 0; h < 2; h++) {
                int row = m0 + mw + i * 16 + lr + h * 8;
                float v0 = acc[i][j][2 * h + 0] + b0;
                float v1 = acc[i][j][2 * h + 1] + b1;
                if (ACT == 0) { v0 = fmaxf(v0, 0.f); v1 = fmaxf(v1, 0.f); }
                else if (ACT == 1) { v0 = 1.f / (1.f + __expf(-v0)); v1 = 1.f / (1.f + __expf(-v1)); }
                size_t gi = (size_t)e * cStride + (size_t)row * ldc + col;
                if (OUTM == 0) {
                    *reinterpret_cast<float2*>(Cf + gi) = make_float2(v0, v1);
                } else {
                    *reinterpret_cast<__half2*>(Ch + gi) = __floats2half2_rn(v0, v1);
                }
            }
        }
}

// ---------------- merged prep: weight transpose + gather + gate pack ----------------
#define WCONV_BLKS 3920
#define GATH_BLKS  2048
#define GPACK_BLKS 257

__global__ void prep_all(const float* __restrict__ s1, const float* __restrict__ s2,
                         const float* __restrict__ s3, const float* __restrict__ s4,
                         const float* __restrict__ s5, const float* __restrict__ s6,
                         const int* __restrict__ ids, const float* __restrict__ emb,
                         const float* __restrict__ Wst1, const float* __restrict__ bst1,
                         const float* __restrict__ Wsh1, const float* __restrict__ bsh1,
                         const float* __restrict__ Wst2, const float* __restrict__ bst2)
{
    __shared__ float t[32][33];
    int b = blockIdx.x;
    int tid = threadIdx.x;

    if (b < WCONV_BLKS) {
        const float* src; f16* dst; int K, N, loc;
        if (b < 1536)      { src = s1; dst = g_w1; K = DIN; N = H1_; loc = b; }
        else if (b < 2304) { src = s2; dst = g_w2; K = H1_; N = H2_; loc = b - 1536; }
        else if (b < 3072) { src = s3; dst = g_w3; K = H2_; N = H1_; loc = b - 2304; }
        else if (b < 3840) { src = s4; dst = g_w4; K = H1_; N = H2_; loc = b - 3072; }
        else if (b < 3904) { src = s5; dst = g_w5; K = H2_; N = T1_; loc = b - 3840; }
        else               { src = s6; dst = g_w6; K = T1_; N = T2_; loc = b - 3904; }
        int tX = N >> 5, tY = K >> 5;
        int e  = loc / (tX * tY);
        int r  = loc % (tX * tY);
        int k0 = (r / tX) * 32, n0 = (r % tX) * 32;
        int tx = tid & 31, ty = tid >> 5;
        #pragma unroll
        for (int j = 0; j < 4; j++)
            t[ty + 8 * j][tx] = src[((size_t)e * K + k0 + ty + 8 * j) * N + n0 + tx];
        __syncthreads();
        #pragma unroll
        for (int j = 0; j < 4; j++) {
            int n = n0 + ty + 8 * j, k = k0 + tx;
            dst[((size_t)e * N + n) * K + k] = __float2half_rn(t[tx][ty + 8 * j]);
        }
    } else if (b < WCONV_BLKS + GATH_BLKS) {
        int idx = (b - WCONV_BLKS) * 256 + tid;      // b*F + f
        int f  = idx & (F_ - 1);
        int id = ids[idx];
        const float4* src = reinterpret_cast<const float4*>(emb + ((size_t)f * V_ + id) * DE);
        float4 v0 = src[0], v1 = src[1], v2 = src[2], v3 = src[3];
        __align__(16) f16 hv[16];
        float vals[16] = {v0.x,v0.y,v0.z,v0.w, v1.x,v1.y,v1.z,v1.w,
                          v2.x,v2.y,v2.z,v2.w, v3.x,v3.y,v3.z,v3.w};
        #pragma unroll
        for (int j = 0; j < 16; j++) hv[j] = __float2half_rn(vals[j]);
        uint4* dh = reinterpret_cast<uint4*>(g_Xf + (size_t)idx * DE);
        dh[0] = ((uint4*)hv)[0]; dh[1] = ((uint4*)hv)[1];
    } else {
        int idx = (b - WCONV_BLKS - GATH_BLKS) * 256 + tid;
        if (idx < 64 * DIN) {
            int r = idx / DIN, d = idx % DIN;
            float v = 0.f;
            if (r < 8)       v = Wst1[(size_t)(r >> 2) * DIN * 4 + d * 4 + (r & 3)];
            else if (r < 14) v = Wsh1[(size_t)d * 6 + (r - 8)];
            g_wg1[(size_t)r * DIN + d] = __float2half_rn(v);
        } else if (idx < 64 * DIN + 2 * 64 * H2_) {
            int q = idx - 64 * DIN;
            int tsk = q / (64 * H2_);
            int rr  = q % (64 * H2_);
            int r = rr / H2_, d = rr % H2_;
            float v = (r < 4) ? Wst2[(size_t)tsk * H2_ * 4 + d * 4 + r] : 0.f;
            g_wg2[((size_t)tsk * 64 + r) * H2_ + d] = __float2half_rn(v);
        } else if (idx < 64 * DIN + 2 * 64 * H2_ + 64) {
            int i = idx - (64 * DIN + 2 * 64 * H2_);
            g_b1p[i] = (i < 8) ? bst1[i] : ((i < 14) ? bsh1[i - 8] : 0.f);
        } else if (idx < 64 * DIN + 2 * 64 * H2_ + 64 + 128) {
            int i = idx - (64 * DIN + 2 * 64 * H2_ + 64);
            int tsk = i >> 6, k = i & 63;
            g_b2p[i] = (k < 4) ? bst2[tsk * 4 + k] : 0.f;
        }
    }
}

// ---------------- uint4 <-> 8 floats ----------------
__device__ __forceinline__ void unpack8(uint4 u, float* f) {
    float2 a = __half22float2(*reinterpret_cast<__half2*>(&u.x));
    float2 b = __half22float2(*reinterpret_cast<__half2*>(&u.y));
    float2 c = __half22float2(*reinterpret_cast<__half2*>(&u.z));
    float2 d = __half22float2(*reinterpret_cast<__half2*>(&u.w));
    f[0]=a.x; f[1]=a.y; f[2]=b.x; f[3]=b.y; f[4]=c.x; f[5]=c.y; f[6]=d.x; f[7]=d.y;
}
__device__ __forceinline__ uint4 pack8(const float* f) {
    uint4 u;
    *reinterpret_cast<__half2*>(&u.x) = __floats2half2_rn(f[0], f[1]);
    *reinterpret_cast<__half2*>(&u.y) = __floats2half2_rn(f[2], f[3]);
    *reinterpret_cast<__half2*>(&u.z) = __floats2half2_rn(f[4], f[5]);
    *reinterpret_cast<__half2*>(&u.w) = __floats2half2_rn(f[6], f[7]);
    return u;
}

// ---------------- level-1 combine (uint4-vectorized: 1 x 16B per expert per lane) -------
__global__ void comb1_kernel() {
    int warp = threadIdx.x >> 5, lane = threadIdx.x & 31;
    int b = blockIdx.x * 8 + warp;

    float lg[14];
    #pragma unroll
    for (int i = 0; i < 14; i++) lg[i] = __ldg(g_L1 + (size_t)b * 64 + i);

    float g0[4], g1[4], gs[6];
    {
        float m = fmaxf(fmaxf(lg[0], lg[1]), fmaxf(lg[2], lg[3]));
        float s = 0.f;
        #pragma unroll
        for (int k = 0; k < 4; k++) { g0[k] = __expf(lg[k] - m); s += g0[k]; }
        #pragma unroll
        for (int k = 0; k < 4; k++) g0[k] /= s;
    }
    {
        float m = fmaxf(fmaxf(lg[4], lg[5]), fmaxf(lg[6], lg[7]));
        float s = 0.f;
        #pragma unroll
        for (int k = 0; k < 4; k++) { g1[k] = __expf(lg[4 + k] - m); s += g1[k]; }
        #pragma unroll
        for (int k = 0; k < 4; k++) g1[k] /= s;
    }
    {
        float m = lg[8];
        #pragma unroll
        for (int k = 9; k < 14; k++) m = fmaxf(m, lg[k]);
        float s = 0.f;
        #pragma unroll
        for (int k = 0; k < 6; k++) { gs[k] = __expf(lg[8 + k] - m); s += gs[k]; }
        #pragma unroll
        for (int k = 0; k < 6; k++) gs[k] /= s;
    }

    // each lane handles 8 consecutive halves; warp covers the full 256-wide row
    const uint4* O4 = reinterpret_cast<const uint4*>(g_O);
    uint4* X24 = reinterpret_cast<uint4*>(g_X2f);
    const int c4 = lane;                            // uint4 index within row (0..31)

    float v[6][8];
    #pragma unroll
    for (int e = 0; e < 6; e++)
        unpack8(O4[((size_t)e * B_ + b) * (H2_ / 8) + c4], v[e]);

    float o0[8], o1[8], os[8];
    #pragma unroll
    for (int q = 0; q < 8; q++) {
        o0[q] = g0[0]*v[0][q] + g0[1]*v[1][q] + g0[2]*v[4][q] + g0[3]*v[5][q];
        o1[q] = g1[0]*v[2][q] + g1[1]*v[3][q] + g1[2]*v[4][q] + g1[3]*v[5][q];
        float s = 0.f;
        #pragma unroll
        for (int e = 0; e < 6; e++) s += gs[e] * v[e][q];
        os[q] = s;
    }
    X24[((size_t)0 * B_ + b) * (H2_ / 8) + c4] = pack8(o0);
    X24[((size_t)1 * B_ + b) * (H2_ / 8) + c4] = pack8(o1);
    X24[((size_t)2 * B_ + b) * (H2_ / 8) + c4] = pack8(os);
}

// ---------------- level-2 combine (uint4-vectorized) ----------------
__global__ void comb2_kernel() {
    int warp = threadIdx.x >> 5, lane = threadIdx.x & 31;
    int b = blockIdx.x * 8 + warp;

    float l0[4], l1[4];
    #pragma unroll
    for (int k = 0; k < 4; k++) {
        l0[k] = __ldg(g_L2 + ((size_t)0 * B_ + b) * 64 + k);
        l1[k] = __ldg(g_L2 + ((size_t)1 * B_ + b) * 64 + k);
    }

    float g0[4], g1[4];
    {
        float m = fmaxf(fmaxf(l0[0], l0[1]), fmaxf(l0[2], l0[3]));
        float s = 0.f;
        #pragma unroll
        for (int k = 0; k < 4; k++) { g0[k] = __expf(l0[k] - m); s += g0[k]; }
        #pragma unroll
        for (int k = 0; k < 4; k++) g0[k] /= s;
    }
    {
        float m = fmaxf(fmaxf(l1[0], l1[1]), fmaxf(l1[2], l1[3]));
        float s = 0.f;
        #pragma unroll
        for (int k = 0; k < 4; k++) { g1[k] = __expf(l1[k] - m); s += g1[k]; }
        #pragma unroll
        for (int k = 0; k < 4; k++) g1[k] /= s;
    }

    const uint4* O4 = reinterpret_cast<const uint4*>(g_O);
    uint4* X34 = reinterpret_cast<uint4*>(g_X3f);
    const int c4 = lane;

    float v[6][8];
    #pragma unroll
    for (int e = 0; e < 6; e++)
        unpack8(O4[((size_t)e * B_ + b) * (H2_ / 8) + c4], v[e]);

    float o0[8], o1[8];
    #pragma unroll
    for (int q = 0; q < 8; q++) {
        o0[q] = g0[0]*v[0][q] + g0[1]*v[1][q] + g0[2]*v[4][q] + g0[3]*v[5][q];
        o1[q] = g1[0]*v[2][q] + g1[1]*v[3][q] + g1[2]*v[4][q] + g1[3]*v[5][q];
    }
    X34[((size_t)0 * B_ + b) * (H2_ / 8) + c4] = pack8(o0);
    X34[((size_t)1 * B_ + b) * (H2_ / 8) + c4] = pack8(o1);
}

// ---------------- launcher ----------------
extern "C" void kernel_launch(void* const* d_in, const int* in_sizes, int n_in,
                              void* d_out, int out_size) {
    const int*   x_ids = (const int*)  d_in[0];
    const float* emb   = (const float*)d_in[1];
    const float* e1_W1 = (const float*)d_in[2];
    const float* e1_b1 = (const float*)d_in[3];
    const float* e1_W2 = (const float*)d_in[4];
    const float* e1_b2 = (const float*)d_in[5];
    const float* g1_Ws = (const float*)d_in[6];
    const float* g1_bs = (const float*)d_in[7];
    const float* g1_Wsh= (const float*)d_in[8];
    const float* g1_bsh= (const float*)d_in[9];
    const float* e2_W1 = (const float*)d_in[10];
    const float* e2_b1 = (const float*)d_in[11];
    const float* e2_W2 = (const float*)d_in[12];
    const float* e2_b2 = (const float*)d_in[13];
    const float* g2_Ws = (const float*)d_in[14];
    const float* g2_bs = (const float*)d_in[15];
    const float* tw_W1 = (const float*)d_in[16];
    const float* tw_b1 = (const float*)d_in[17];
    const float* tw_W2 = (const float*)d_in[18];
    const float* tw_b2 = (const float*)d_in[19];

    f16 *pXf,*pHf,*pO,*pX2f,*pX3f,*pTf,*w1,*w2,*w3,*w4,*w5,*w6,*wg1,*wg2;
    float *pL1,*pL2,*b1p,*b2p;
    cudaGetSymbolAddress((void**)&pXf,  g_Xf);
    cudaGetSymbolAddress((void**)&pHf,  g_Hf);
    cudaGetSymbolAddress((void**)&pO,   g_O);
    cudaGetSymbolAddress((void**)&pX2f, g_X2f);
    cudaGetSymbolAddress((void**)&pX3f, g_X3f);
    cudaGetSymbolAddress((void**)&pTf,  g_Tf);
    cudaGetSymbolAddress((void**)&pL1,  g_L1);
    cudaGetSymbolAddress((void**)&pL2,  g_L2);
    cudaGetSymbolAddress((void**)&w1, g_w1);
    cudaGetSymbolAddress((void**)&w2, g_w2);
    cudaGetSymbolAddress((void**)&w3, g_w3);
    cudaGetSymbolAddress((void**)&w4, g_w4);
    cudaGetSymbolAddress((void**)&w5, g_w5);
    cudaGetSymbolAddress((void**)&w6, g_w6);
    cudaGetSymbolAddress((void**)&wg1, g_wg1);
    cudaGetSymbolAddress((void**)&wg2, g_wg2);
    cudaGetSymbolAddress((void**)&b1p, g_b1p);
    cudaGetSymbolAddress((void**)&b2p, g_b2p);

    const int SM128 = 2 * (128 * 128 + 128 * 128);   // 65536 (2 stages)
    const int SM64  = 2 * (128 * 128 + 64 * 128);    // 49152
    cudaFuncSetAttribute((const void*)gemm_mma<128,0,1>, cudaFuncAttributeMaxDynamicSharedMemorySize, SM128);
    cudaFuncSetAttribute((const void*)gemm_mma<64,2,0>,  cudaFuncAttributeMaxDynamicSharedMemorySize, SM64);
    cudaFuncSetAttribute((const void*)gemm_mma<64,1,0>,  cudaFuncAttributeMaxDynamicSharedMemorySize, SM64);

    // prep (single launch: weight transpose + gather + gate pack — all coalesced)
    prep_all<<<WCONV_BLKS + GATH_BLKS + GPACK_BLKS, 256>>>(
        e1_W1, e1_W2, e2_W1, e2_W2, tw_W1, tw_W2,
        x_ids, emb, g1_Ws, g1_bs, g1_Wsh, g1_bsh, g2_Ws, g2_bs);

    // L1 experts
    gemm_mma<128,0,1><<<dim3(H1_/128, B_/128, NE), 128, SM128>>>(
        pXf, w1, e1_b1, nullptr, pHf, DIN, H1_, 0, 0, (size_t)B_*H1_, H1_);
    gemm_mma<128,0,1><<<dim3(H2_/128, B_/128, NE), 128, SM128>>>(
        pHf, w2, e1_b2, nullptr, pO, H1_, H2_, 2, (size_t)B_*H1_, (size_t)B_*H2_, H2_);
    // L1 gate logits + combine
    gemm_mma<64,2,0><<<dim3(1, B_/128, 1), 128, SM64>>>(
        pXf, wg1, b1p, pL1, nullptr, DIN, 64, 0, 0, 0, 64);
    comb1_kernel<<<B_/8, 256>>>();

    // L2 experts
    gemm_mma<128,0,1><<<dim3(H1_/128, B_/128, NE), 128, SM128>>>(
        pX2f, w3, e2_b1, nullptr, pHf, H2_, H1_, 1, (size_t)B_*H2_, (size_t)B_*H1_, H1_);
    gemm_mma<128,0,1><<<dim3(H2_/128, B_/128, NE), 128, SM128>>>(
        pHf, w4, e2_b2, nullptr, pO, H1_, H2_, 2, (size_t)B_*H1_, (size_t)B_*H2_, H2_);
    // L2 gate logits + combine
    gemm_mma<64,2,0><<<dim3(1, B_/128, 2), 128, SM64>>>(
        pX2f, wg2, b2p, pL2, nullptr, H2_, 64, 2, (size_t)B_*H2_, (size_t)B_*64, 64);
    comb2_kernel<<<B_/8, 256>>>();

    // towers
    gemm_mma<128,0,1><<<dim3(T1_/128, B_/128, 2), 128, SM128>>>(
        pX3f, w5, tw_b1, nullptr, pTf, H2_, T1_, 2, (size_t)B_*H2_, (size_t)B_*T1_, T1_);
    gemm_mma<64,1,0><<<dim3(T2_/64, B_/128, 2), 128, SM64>>>(
        pTf, w6, tw_b2, (float*)d_out, nullptr, T1_, T2_, 2, (size_t)B_*T1_, (size_t)T2_, 2*T2_);
}

// round 15
// speedup vs baseline: 1.0340x; 1.0015x over previous
#include <cuda_runtime.h>
#include <cuda_fp16.h>
#include <math.h>
#include <stdint.h>

typedef __half f16;

#define B_   16384
#define F_   32
#define V_   50000
#define DE   16
#define DIN  512
#define NE   6
#define H1_  512
#define H2_  256
#define T1_  128
#define T2_  64

// ---------------- scratch (device globals; no runtime alloc) ----------------
__device__ __align__(256) f16 g_Xf [(size_t)B_*DIN];
__device__ __align__(256) f16 g_Hf [(size_t)NE*B_*H1_];
__device__ __align__(256) f16 g_O  [(size_t)NE*B_*H2_];
__device__ __align__(256) f16 g_X2f[(size_t)3*B_*H2_];
__device__ __align__(256) f16 g_X3f[(size_t)2*B_*H2_];
__device__ __align__(256) f16 g_Tf [(size_t)2*B_*T1_];
__device__ __align__(256) float g_L1[(size_t)B_*64];
__device__ __align__(256) float g_L2[(size_t)2*B_*64];
// transposed fp16 weights, layout [E, N, K] (K-major rows)
__device__ __align__(256) f16 g_w1[(size_t)NE*H1_*DIN];
__device__ __align__(256) f16 g_w2[(size_t)NE*H2_*H1_];
__device__ __align__(256) f16 g_w3[(size_t)NE*H1_*H2_];
__device__ __align__(256) f16 g_w4[(size_t)NE*H2_*H1_];
__device__ __align__(256) f16 g_w5[(size_t)2*T1_*H2_];
__device__ __align__(256) f16 g_w6[(size_t)2*T2_*T1_];
// packed gate weights (padded to N=64) + biases
__device__ __align__(256) f16   g_wg1[(size_t)64*DIN];
__device__ __align__(256) f16   g_wg2[(size_t)2*64*H2_];
__device__ __align__(256) float g_b1p[64];
__device__ __align__(256) float g_b2p[128];

// ---------------- helpers ----------------
__device__ __forceinline__ uint32_t smem_u32(const void* p) {
    uint32_t a;
    asm("{ .reg .u64 t; cvta.to.shared.u64 t, %1; cvt.u32.u64 %0, t; }" : "=r"(a) : "l"(p));
    return a;
}
__device__ __forceinline__ void cp16(uint32_t dst, const void* src) {
    asm volatile("cp.async.cg.shared.global [%0], [%1], 16;" :: "r"(dst), "l"(src));
}
template<int N> __device__ __forceinline__ void waitg() {
    asm volatile("cp.async.wait_group %0;" :: "n"(N) : "memory");
}
__device__ __forceinline__ void ldsm4(uint32_t* r, uint32_t a) {
    asm volatile("ldmatrix.sync.aligned.m8n8.x4.shared.b16 {%0,%1,%2,%3}, [%4];"
                 : "=r"(r[0]), "=r"(r[1]), "=r"(r[2]), "=r"(r[3]) : "r"(a));
}
__device__ __forceinline__ void mma16816(float* c, const uint32_t* a, const uint32_t* b) {
    asm volatile("mma.sync.aligned.m16n8k16.row.col.f32.f16.f16.f32 "
                 "{%0,%1,%2,%3}, {%4,%5,%6,%7}, {%8,%9}, {%0,%1,%2,%3};"
                 : "+f"(c[0]), "+f"(c[1]), "+f"(c[2]), "+f"(c[3])
                 : "r"(a[0]), "r"(a[1]), "r"(a[2]), "r"(a[3]), "r"(b[0]), "r"(b[1]));
}
__device__ __forceinline__ uint32_t swz(uint32_t off) { return off ^ ((off >> 3) & 0x70); }

// ---------------- fp16 grouped GEMM, 4 warps, 64x(NT/2) warp tiles ----------------
// C[e] = act(A[aidx] @ B[e]^T + bias[e])
// NT: CTA N-tile (128/64). ACT: 0=relu 1=sigmoid 2=none. OUTM: 0=f32, 1=f16.
// ST: cp.async pipeline stages (2 = proven big-GEMM path; 4 = latency-bound small GEMMs)
template<int NT, int ACT, int OUTM, int ST>
__global__ void __launch_bounds__(128, 2)
gemm_mma(const f16* __restrict__ A, const f16* __restrict__ B,
         const float* __restrict__ bias,
         float* __restrict__ Cf, f16* __restrict__ Ch,
         int K, int Ntot, int a_sel, size_t aStride, size_t cStride, int ldc)
{
    extern __shared__ char smem_raw[];
    constexpr int ASTG  = 128 * 128;
    constexpr int BSTG  = NT * 128;
    constexpr int STAGE = ASTG + BSTG;
    constexpr int WN    = NT / 2;
    constexpr int NJ    = WN / 8;
    constexpr int NB    = WN / 16;

    const int tid  = threadIdx.x;
    const int wid  = tid >> 5;
    const int lane = tid & 31;
    const int e  = blockIdx.z;
    const int m0 = blockIdx.y * 128;
    const int n0 = blockIdx.x * NT;

    const int aidx = (a_sel == 0) ? 0 : ((a_sel == 1) ? (e >> 1) : e);
    const f16* pA = A + (size_t)aidx * aStride + (size_t)m0 * K;
    const f16* pB = B + ((size_t)e * Ntot + n0) * K;

    const uint32_t sb = smem_u32(smem_raw);

    const int wm = wid >> 1, wn = wid & 1;
    const int mw = wm * 64;
    const int nw = wn * WN;

    float acc[4][NJ][4];
    #pragma unroll
    for (int i = 0; i < 4; i++)
        #pragma unroll
        for (int j = 0; j < NJ; j++)
            #pragma unroll
            for (int q = 0; q < 4; q++) acc[i][j][q] = 0.f;

    auto load_stage = [&](int kt, int st) {
        const uint32_t base = sb + st * STAGE;
        const int k0 = kt * 64;
        #pragma unroll
        for (int t = 0; t < 8; t++) {
            int id = tid + t * 128;
            int r = id >> 3, q = id & 7;
            uint32_t off = swz((uint32_t)(r * 128 + q * 16));
            cp16(base + off, pA + (size_t)r * K + k0 + q * 8);
        }
        #pragma unroll
        for (int t = 0; t < NT / 16; t++) {
            int id = tid + t * 128;
            int r = id >> 3, q = id & 7;
            uint32_t off = swz((uint32_t)(r * 128 + q * 16));
            cp16(base + ASTG + off, pB + (size_t)r * K + k0 + q * 8);
        }
        asm volatile("cp.async.commit_group;" ::: "memory");
    };

    const int T = K >> 6;

    if (ST == 2) {
        // proven 2-stage double-sync path (bit-identical to R14)
        load_stage(0, 0);
        for (int kt = 0; kt < T; kt++) {
            if (kt + 1 < T) { load_stage(kt + 1, (kt + 1) & 1); waitg<1>(); }
            else            { waitg<0>(); }
            __syncthreads();

            const uint32_t abase = sb + (kt & 1) * STAGE;
            const uint32_t bbase = abase + ASTG;
            #pragma unroll
            for (int ks = 0; ks < 4; ks++) {
                const int cb = ks * 32 + (lane >> 4) * 16;
                uint32_t af[4][4];
                #pragma unroll
                for (int i = 0; i < 4; i++) {
                    int row = mw + i * 16 + (lane & 15);
                    ldsm4(af[i], abase + swz((uint32_t)(row * 128 + cb)));
                }
                uint32_t bf[NJ][2];
                #pragma unroll
                for (int bb = 0; bb < NB; bb++) {
                    int row = nw + bb * 16 + (lane & 15);
                    uint32_t tr[4];
                    ldsm4(tr, bbase + swz((uint32_t)(row * 128 + cb)));
                    bf[2*bb][0] = tr[0]; bf[2*bb+1][0] = tr[1];
                    bf[2*bb][1] = tr[2]; bf[2*bb+1][1] = tr[3];
                }
                #pragma unroll
                for (int i = 0; i < 4; i++)
                    #pragma unroll
                    for (int j = 0; j < NJ; j++)
                        mma16816(acc[i][j], af[i], bf[j]);
            }
            __syncthreads();
        }
    } else {
        // ST-stage single-sync path (R9-validated ordering), for latency-bound GEMMs
        #pragma unroll
        for (int p = 0; p < ST - 1; p++)
            if (p < T) load_stage(p, p);
        for (int kt = 0; kt < T; kt++) {
            int rem = T - 1 - kt;
            if (rem >= ST - 2)      waitg<ST - 2>();
            else if (rem == 2)      waitg<2>();
            else if (rem == 1)      waitg<1>();
            else                    waitg<0>();
            __syncthreads();

            if (kt + ST - 1 < T) load_stage(kt + ST - 1, (kt + ST - 1) % ST);

            const uint32_t abase = sb + (kt % ST) * STAGE;
            const uint32_t bbase = abase + ASTG;
            #pragma unroll
            for (int ks = 0; ks < 4; ks++) {
                const int cb = ks * 32 + (lane >> 4) * 16;
                uint32_t af[4][4];
                #pragma unroll
                for (int i = 0; i < 4; i++) {
                    int row = mw + i * 16 + (lane & 15);
                    ldsm4(af[i], abase + swz((uint32_t)(row * 128 + cb)));
                }
                uint32_t bf[NJ][2];
                #pragma unroll
                for (int bb = 0; bb < NB; bb++) {
                    int row = nw + bb * 16 + (lane & 15);
                    uint32_t tr[4];
                    ldsm4(tr, bbase + swz((uint32_t)(row * 128 + cb)));
                    bf[2*bb][0] = tr[0]; bf[2*bb+1][0] = tr[1];
                    bf[2*bb][1] = tr[2]; bf[2*bb+1][1] = tr[3];
                }
                #pragma unroll
                for (int i = 0; i < 4; i++)
                    #pragma unroll
                    for (int j = 0; j < NJ; j++)
                        mma16816(acc[i][j], af[i], bf[j]);
            }
        }
        __syncthreads();
    }

    // epilogue
    const int lr  = lane >> 2;
    const int lc2 = (lane & 3) * 2;
    #pragma unroll
    for (int i = 0; i < 4; i++)
        #pragma unroll
        for (int j = 0; j < NJ; j++) {
            int col = n0 + nw + j * 8 + lc2;
            float b0 = __ldg(bias + (size_t)e * Ntot + col);
            float b1 = __ldg(bias + (size_t)e * Ntot + col + 1);
            #pragma unroll
            for (int h = 0; h < 2; h++) {
                int row = m0 + mw + i * 16 + lr + h * 8;
                float v0 = acc[i][j][2 * h + 0] + b0;
                float v1 = acc[i][j][2 * h + 1] + b1;
                if (ACT == 0) { v0 = fmaxf(v0, 0.f); v1 = fmaxf(v1, 0.f); }
                else if (ACT == 1) { v0 = 1.f / (1.f + __expf(-v0)); v1 = 1.f / (1.f + __expf(-v1)); }
                size_t gi = (size_t)e * cStride + (size_t)row * ldc + col;
                if (OUTM == 0) {
                    *reinterpret_cast<float2*>(Cf + gi) = make_float2(v0, v1);
                } else {
                    *reinterpret_cast<__half2*>(Ch + gi) = __floats2half2_rn(v0, v1);
                }
            }
        }
}

// ---------------- merged prep: weight transpose + gather + gate pack ----------------
#define WCONV_BLKS 3920
#define GATH_BLKS  2048
#define GPACK_BLKS 257

__global__ void prep_all(const float* __restrict__ s1, const float* __restrict__ s2,
                         const float* __restrict__ s3, const float* __restrict__ s4,
                         const float* __restrict__ s5, const float* __restrict__ s6,
                         const int* __restrict__ ids, const float* __restrict__ emb,
                         const float* __restrict__ Wst1, const float* __restrict__ bst1,
                         const float* __restrict__ Wsh1, const float* __restrict__ bsh1,
                         const float* __restrict__ Wst2, const float* __restrict__ bst2)
{
    __shared__ float t[32][33];
    int b = blockIdx.x;
    int tid = threadIdx.x;

    if (b < WCONV_BLKS) {
        const float* src; f16* dst; int K, N, loc;
        if (b < 1536)      { src = s1; dst = g_w1; K = DIN; N = H1_; loc = b; }
        else if (b < 2304) { src = s2; dst = g_w2; K = H1_; N = H2_; loc = b - 1536; }
        else if (b < 3072) { src = s3; dst = g_w3; K = H2_; N = H1_; loc = b - 2304; }
        else if (b < 3840) { src = s4; dst = g_w4; K = H1_; N = H2_; loc = b - 3072; }
        else if (b < 3904) { src = s5; dst = g_w5; K = H2_; N = T1_; loc = b - 3840; }
        else               { src = s6; dst = g_w6; K = T1_; N = T2_; loc = b - 3904; }
        int tX = N >> 5, tY = K >> 5;
        int e  = loc / (tX * tY);
        int r  = loc % (tX * tY);
        int k0 = (r / tX) * 32, n0 = (r % tX) * 32;
        int tx = tid & 31, ty = tid >> 5;
        #pragma unroll
        for (int j = 0; j < 4; j++)
            t[ty + 8 * j][tx] = src[((size_t)e * K + k0 + ty + 8 * j) * N + n0 + tx];
        __syncthreads();
        #pragma unroll
        for (int j = 0; j < 4; j++) {
            int n = n0 + ty + 8 * j, k = k0 + tx;
            dst[((size_t)e * N + n) * K + k] = __float2half_rn(t[tx][ty + 8 * j]);
        }
    } else if (b < WCONV_BLKS + GATH_BLKS) {
        int idx = (b - WCONV_BLKS) * 256 + tid;      // b*F + f
        int f  = idx & (F_ - 1);
        int id = ids[idx];
        const float4* src = reinterpret_cast<const float4*>(emb + ((size_t)f * V_ + id) * DE);
        float4 v0 = src[0], v1 = src[1], v2 = src[2], v3 = src[3];
        __align__(16) f16 hv[16];
        float vals[16] = {v0.x,v0.y,v0.z,v0.w, v1.x,v1.y,v1.z,v1.w,
                          v2.x,v2.y,v2.z,v2.w, v3.x,v3.y,v3.z,v3.w};
        #pragma unroll
        for (int j = 0; j < 16; j++) hv[j] = __float2half_rn(vals[j]);
        uint4* dh = reinterpret_cast<uint4*>(g_Xf + (size_t)idx * DE);
        dh[0] = ((uint4*)hv)[0]; dh[1] = ((uint4*)hv)[1];
    } else {
        int idx = (b - WCONV_BLKS - GATH_BLKS) * 256 + tid;
        if (idx < 64 * DIN) {
            int r = idx / DIN, d = idx % DIN;
            float v = 0.f;
            if (r < 8)       v = Wst1[(size_t)(r >> 2) * DIN * 4 + d * 4 + (r & 3)];
            else if (r < 14) v = Wsh1[(size_t)d * 6 + (r - 8)];
            g_wg1[(size_t)r * DIN + d] = __float2half_rn(v);
        } else if (idx < 64 * DIN + 2 * 64 * H2_) {
            int q = idx - 64 * DIN;
            int tsk = q / (64 * H2_);
            int rr  = q % (64 * H2_);
            int r = rr / H2_, d = rr % H2_;
            float v = (r < 4) ? Wst2[(size_t)tsk * H2_ * 4 + d * 4 + r] : 0.f;
            g_wg2[((size_t)tsk * 64 + r) * H2_ + d] = __float2half_rn(v);
        } else if (idx < 64 * DIN + 2 * 64 * H2_ + 64) {
            int i = idx - (64 * DIN + 2 * 64 * H2_);
            g_b1p[i] = (i < 8) ? bst1[i] : ((i < 14) ? bsh1[i - 8] : 0.f);
        } else if (idx < 64 * DIN + 2 * 64 * H2_ + 64 + 128) {
            int i = idx - (64 * DIN + 2 * 64 * H2_ + 64);
            int tsk = i >> 6, k = i & 63;
            g_b2p[i] = (k < 4) ? bst2[tsk * 4 + k] : 0.f;
        }
    }
}

// ---------------- uint4 <-> 8 floats ----------------
__device__ __forceinline__ void unpack8(uint4 u, float* f) {
    float2 a = __half22float2(*reinterpret_cast<__half2*>(&u.x));
    float2 b = __half22float2(*reinterpret_cast<__half2*>(&u.y));
    float2 c = __half22float2(*reinterpret_cast<__half2*>(&u.z));
    float2 d = __half22float2(*reinterpret_cast<__half2*>(&u.w));
    f[0]=a.x; f[1]=a.y; f[2]=b.x; f[3]=b.y; f[4]=c.x; f[5]=c.y; f[6]=d.x; f[7]=d.y;
}
__device__ __forceinline__ uint4 pack8(const float* f) {
    uint4 u;
    *reinterpret_cast<__half2*>(&u.x) = __floats2half2_rn(f[0], f[1]);
    *reinterpret_cast<__half2*>(&u.y) = __floats2half2_rn(f[2], f[3]);
    *reinterpret_cast<__half2*>(&u.z) = __floats2half2_rn(f[4], f[5]);
    *reinterpret_cast<__half2*>(&u.w) = __floats2half2_rn(f[6], f[7]);
    return u;
}

// ---------------- level-1 combine (uint4-vectorized) ----------------
__global__ void comb1_kernel() {
    int warp = threadIdx.x >> 5, lane = threadIdx.x & 31;
    int b = blockIdx.x * 8 + warp;

    float lg[14];
    #pragma unroll
    for (int i = 0; i < 14; i++) lg[i] = __ldg(g_L1 + (size_t)b * 64 + i);

    float g0[4], g1[4], gs[6];
    {
        float m = fmaxf(fmaxf(lg[0], lg[1]), fmaxf(lg[2], lg[3]));
        float s = 0.f;
        #pragma unroll
        for (int k = 0; k < 4; k++) { g0[k] = __expf(lg[k] - m); s += g0[k]; }
        #pragma unroll
        for (int k = 0; k < 4; k++) g0[k] /= s;
    }
    {
        float m = fmaxf(fmaxf(lg[4], lg[5]), fmaxf(lg[6], lg[7]));
        float s = 0.f;
        #pragma unroll
        for (int k = 0; k < 4; k++) { g1[k] = __expf(lg[4 + k] - m); s += g1[k]; }
        #pragma unroll
        for (int k = 0; k < 4; k++) g1[k] /= s;
    }
    {
        float m = lg[8];
        #pragma unroll
        for (int k = 9; k < 14; k++) m = fmaxf(m, lg[k]);
        float s = 0.f;
        #pragma unroll
        for (int k = 0; k < 6; k++) { gs[k] = __expf(lg[8 + k] - m); s += gs[k]; }
        #pragma unroll
        for (int k = 0; k < 6; k++) gs[k] /= s;
    }

    const uint4* O4 = reinterpret_cast<const uint4*>(g_O);
    uint4* X24 = reinterpret_cast<uint4*>(g_X2f);
    const int c4 = lane;

    float v[6][8];
    #pragma unroll
    for (int e = 0; e < 6; e++)
        unpack8(O4[((size_t)e * B_ + b) * (H2_ / 8) + c4], v[e]);

    float o0[8], o1[8], os[8];
    #pragma unroll
    for (int q = 0; q < 8; q++) {
        o0[q] = g0[0]*v[0][q] + g0[1]*v[1][q] + g0[2]*v[4][q] + g0[3]*v[5][q];
        o1[q] = g1[0]*v[2][q] + g1[1]*v[3][q] + g1[2]*v[4][q] + g1[3]*v[5][q];
        float s = 0.f;
        #pragma unroll
        for (int e = 0; e < 6; e++) s += gs[e] * v[e][q];
        os[q] = s;
    }
    X24[((size_t)0 * B_ + b) * (H2_ / 8) + c4] = pack8(o0);
    X24[((size_t)1 * B_ + b) * (H2_ / 8) + c4] = pack8(o1);
    X24[((size_t)2 * B_ + b) * (H2_ / 8) + c4] = pack8(os);
}

// ---------------- level-2 combine (uint4-vectorized) ----------------
__global__ void comb2_kernel() {
    int warp = threadIdx.x >> 5, lane = threadIdx.x & 31;
    int b = blockIdx.x * 8 + warp;

    float l0[4], l1[4];
    #pragma unroll
    for (int k = 0; k < 4; k++) {
        l0[k] = __ldg(g_L2 + ((size_t)0 * B_ + b) * 64 + k);
        l1[k] = __ldg(g_L2 + ((size_t)1 * B_ + b) * 64 + k);
    }

    float g0[4], g1[4];
    {
        float m = fmaxf(fmaxf(l0[0], l0[1]), fmaxf(l0[2], l0[3]));
        float s = 0.f;
        #pragma unroll
        for (int k = 0; k < 4; k++) { g0[k] = __expf(l0[k] - m); s += g0[k]; }
        #pragma unroll
        for (int k = 0; k < 4; k++) g0[k] /= s;
    }
    {
        float m = fmaxf(fmaxf(l1[0], l1[1]), fmaxf(l1[2], l1[3]));
        float s = 0.f;
        #pragma unroll
        for (int k = 0; k < 4; k++) { g1[k] = __expf(l1[k] - m); s += g1[k]; }
        #pragma unroll
        for (int k = 0; k < 4; k++) g1[k] /= s;
    }

    const uint4* O4 = reinterpret_cast<const uint4*>(g_O);
    uint4* X34 = reinterpret_cast<uint4*>(g_X3f);
    const int c4 = lane;

    float v[6][8];
    #pragma unroll
    for (int e = 0; e < 6; e++)
        unpack8(O4[((size_t)e * B_ + b) * (H2_ / 8) + c4], v[e]);

    float o0[8], o1[8];
    #pragma unroll
    for (int q = 0; q < 8; q++) {
        o0[q] = g0[0]*v[0][q] + g0[1]*v[1][q] + g0[2]*v[4][q] + g0[3]*v[5][q];
        o1[q] = g1[0]*v[2][q] + g1[1]*v[3][q] + g1[2]*v[4][q] + g1[3]*v[5][q];
    }
    X34[((size_t)0 * B_ + b) * (H2_ / 8) + c4] = pack8(o0);
    X34[((size_t)1 * B_ + b) * (H2_ / 8) + c4] = pack8(o1);
}

// ---------------- launcher ----------------
extern "C" void kernel_launch(void* const* d_in, const int* in_sizes, int n_in,
                              void* d_out, int out_size) {
    const int*   x_ids = (const int*)  d_in[0];
    const float* emb   = (const float*)d_in[1];
    const float* e1_W1 = (const float*)d_in[2];
    const float* e1_b1 = (const float*)d_in[3];
    const float* e1_W2 = (const float*)d_in[4];
    const float* e1_b2 = (const float*)d_in[5];
    const float* g1_Ws = (const float*)d_in[6];
    const float* g1_bs = (const float*)d_in[7];
    const float* g1_Wsh= (const float*)d_in[8];
    const float* g1_bsh= (const float*)d_in[9];
    const float* e2_W1 = (const float*)d_in[10];
    const float* e2_b1 = (const float*)d_in[11];
    const float* e2_W2 = (const float*)d_in[12];
    const float* e2_b2 = (const float*)d_in[13];
    const float* g2_Ws = (const float*)d_in[14];
    const float* g2_bs = (const float*)d_in[15];
    const float* tw_W1 = (const float*)d_in[16];
    const float* tw_b1 = (const float*)d_in[17];
    const float* tw_W2 = (const float*)d_in[18];
    const float* tw_b2 = (const float*)d_in[19];

    f16 *pXf,*pHf,*pO,*pX2f,*pX3f,*pTf,*w1,*w2,*w3,*w4,*w5,*w6,*wg1,*wg2;
    float *pL1,*pL2,*b1p,*b2p;
    cudaGetSymbolAddress((void**)&pXf,  g_Xf);
    cudaGetSymbolAddress((void**)&pHf,  g_Hf);
    cudaGetSymbolAddress((void**)&pO,   g_O);
    cudaGetSymbolAddress((void**)&pX2f, g_X2f);
    cudaGetSymbolAddress((void**)&pX3f, g_X3f);
    cudaGetSymbolAddress((void**)&pTf,  g_Tf);
    cudaGetSymbolAddress((void**)&pL1,  g_L1);
    cudaGetSymbolAddress((void**)&pL2,  g_L2);
    cudaGetSymbolAddress((void**)&w1, g_w1);
    cudaGetSymbolAddress((void**)&w2, g_w2);
    cudaGetSymbolAddress((void**)&w3, g_w3);
    cudaGetSymbolAddress((void**)&w4, g_w4);
    cudaGetSymbolAddress((void**)&w5, g_w5);
    cudaGetSymbolAddress((void**)&w6, g_w6);
    cudaGetSymbolAddress((void**)&wg1, g_wg1);
    cudaGetSymbolAddress((void**)&wg2, g_wg2);
    cudaGetSymbolAddress((void**)&b1p, g_b1p);
    cudaGetSymbolAddress((void**)&b2p, g_b2p);

    const int SM128  = 2 * (128 * 128 + 128 * 128);  // 65536 (big GEMMs, 2 stages)
    const int SM64_4 = 4 * (128 * 128 + 64 * 128);   // 98304 (small GEMMs, 4 stages)
    cudaFuncSetAttribute((const void*)gemm_mma<128,0,1,2>, cudaFuncAttributeMaxDynamicSharedMemorySize, SM128);
    cudaFuncSetAttribute((const void*)gemm_mma<64,2,0,4>,  cudaFuncAttributeMaxDynamicSharedMemorySize, SM64_4);
    cudaFuncSetAttribute((const void*)gemm_mma<64,1,0,4>,  cudaFuncAttributeMaxDynamicSharedMemorySize, SM64_4);

    // prep (single launch: weight transpose + gather + gate pack — all coalesced)
    prep_all<<<WCONV_BLKS + GATH_BLKS + GPACK_BLKS, 256>>>(
        e1_W1, e1_W2, e2_W1, e2_W2, tw_W1, tw_W2,
        x_ids, emb, g1_Ws, g1_bs, g1_Wsh, g1_bsh, g2_Ws, g2_bs);

    // L1 experts
    gemm_mma<128,0,1,2><<<dim3(H1_/128, B_/128, NE), 128, SM128>>>(
        pXf, w1, e1_b1, nullptr, pHf, DIN, H1_, 0, 0, (size_t)B_*H1_, H1_);
    gemm_mma<128,0,1,2><<<dim3(H2_/128, B_/128, NE), 128, SM128>>>(
        pHf, w2, e1_b2, nullptr, pO, H1_, H2_, 2, (size_t)B_*H1_, (size_t)B_*H2_, H2_);
    // L1 gate logits (4-stage pipeline) + combine
    gemm_mma<64,2,0,4><<<dim3(1, B_/128, 1), 128, SM64_4>>>(
        pXf, wg1, b1p, pL1, nullptr, DIN, 64, 0, 0, 0, 64);
    comb1_kernel<<<B_/8, 256>>>();

    // L2 experts
    gemm_mma<128,0,1,2><<<dim3(H1_/128, B_/128, NE), 128, SM128>>>(
        pX2f, w3, e2_b1, nullptr, pHf, H2_, H1_, 1, (size_t)B_*H2_, (size_t)B_*H1_, H1_);
    gemm_mma<128,0,1,2><<<dim3(H2_/128, B_/128, NE), 128, SM128>>>(
        pHf, w4, e2_b2, nullptr, pO, H1_, H2_, 2, (size_t)B_*H1_, (size_t)B_*H2_, H2_);
    // L2 gate logits (4-stage pipeline) + combine
    gemm_mma<64,2,0,4><<<dim3(1, B_/128, 2), 128, SM64_4>>>(
        pX2f, wg2, b2p, pL2, nullptr, H2_, 64, 2, (size_t)B_*H2_, (size_t)B_*64, 64);
    comb2_kernel<<<B_/8, 256>>>();

    // towers
    gemm_mma<128,0,1,2><<<dim3(T1_/128, B_/128, 2), 128, SM128>>>(
        pX3f, w5, tw_b1, nullptr, pTf, H2_, T1_, 2, (size_t)B_*H2_, (size_t)B_*T1_, T1_);
    gemm_mma<64,1,0,4><<<dim3(T2_/64, B_/128, 2), 128, SM64_4>>>(
        pTf, w6, tw_b2, (float*)d_out, nullptr, T1_, T2_, 2, (size_t)B_*T1_, (size_t)T2_, 2*T2_);
}